// round 1
// baseline (speedup 1.0000x reference)
#include <cuda_runtime.h>
#include <cstdint>
#include <math.h>

// ---------------- problem constants ----------------
#define B_    4
#define S_    512
#define NS_   8192
#define MAXW  16
#define H_    256
#define NH_   4
#define DH_   64
#define FF_   1024
#define NSPAN (B_*NS_)          // 32768
#define NEGV  (-1000000000.0f)

// ---------------- scratch (device globals; no allocations allowed) ----------
__device__ float g_TR[B_*S_*H_];               // token_reps + pos-encoding (2 MB)
__device__ float g_QK[NH_*H_];                 // folded q@w_k per head (scaled 1/8)
__device__ float g_LB[NH_];                    // logit bias from b_qkv[1] (softmax-invariant, kept for exactness)
__device__ float g_BO[H_];                     // b_qkv[2]@w_o^T + b_o + dummy_query
__device__ float g_M[NH_*H_*H_];               // fused v->o matrix (1024 x 256)
__device__ float g_XP[(size_t)NSPAN*NH_*H_];   // pooled tokens per span (134 MB)
__device__ float g_T1[(size_t)NSPAN*H_];       // out1 / out2 (reused)
__device__ float g_Y [(size_t)NSPAN*H_];       // post-LN1
__device__ float g_F [(size_t)NSPAN*FF_];      // FFN hidden (134 MB)
__device__ int   g_mask_is_byte;

// ---------------- mask format detection -------------------------------------
__global__ void k_detect_mask(const unsigned int* __restrict__ m) {
    __shared__ int found;
    if (threadIdx.x == 0) found = 0;
    __syncthreads();
    unsigned v = m[threadIdx.x];          // first 1024 bytes: safe for both formats
    if (v > 1u) atomicOr(&found, 1);
    __syncthreads();
    if (threadIdx.x == 0) g_mask_is_byte = found;
}

__device__ __forceinline__ int read_mask(const void* p, int i) {
    if (g_mask_is_byte) return ((const unsigned char*)p)[i] != 0;
    return ((const int*)p)[i] != 0;
}

// ---------------- tiny precompute: q, qk, logit bias, output bias -----------
__global__ void k_precompute(const float* __restrict__ dq, const float* __restrict__ wq,
                             const float* __restrict__ wk, const float* __restrict__ bqkv,
                             const float* __restrict__ wo, const float* __restrict__ bo) {
    __shared__ float qs[H_];
    int t = threadIdx.x;
    float s = bqkv[t];                             // b_qkv[0][t]
    for (int c = 0; c < H_; c++) s += dq[c] * wq[t*H_ + c];
    qs[t] = s;
    __syncthreads();
    #pragma unroll
    for (int h = 0; h < NH_; h++) {
        float acc = 0.f;
        for (int d = 0; d < DH_; d++) acc += qs[h*DH_ + d] * wk[(h*DH_ + d)*H_ + t];
        g_QK[h*H_ + t] = 0.125f * acc;             // 1/sqrt(DH)
    }
    if (t < NH_) {
        float acc = 0.f;
        for (int d = 0; d < DH_; d++) acc += qs[t*DH_ + d] * bqkv[H_ + t*DH_ + d];
        g_LB[t] = 0.125f * acc;
    }
    float bacc = bo[t] + dq[t];
    for (int i = 0; i < H_; i++) bacc += bqkv[2*H_ + i] * wo[t*H_ + i];
    g_BO[t] = bacc;
}

// ---------------- M[h*256+c][j] = sum_d w_v[h*64+d][c] * w_o[j][h*64+d] -----
__global__ void k_buildM(const float* __restrict__ wv, const float* __restrict__ wo) {
    __shared__ float wvs[DH_];
    int bid = blockIdx.x;                // h*256 + c
    int h = bid >> 8, c = bid & 255;
    int t = threadIdx.x;                 // j
    if (t < DH_) wvs[t] = wv[(h*DH_ + t)*H_ + c];
    __syncthreads();
    float acc = 0.f;
    #pragma unroll 8
    for (int d = 0; d < DH_; d++) acc += wvs[d] * wo[t*H_ + h*DH_ + d];
    g_M[(size_t)bid*H_ + t] = acc;
}

// ---------------- token_reps + positional encoding --------------------------
__global__ void k_addpe(const float* __restrict__ tok) {
    int idx = blockIdx.x * 256 + threadIdx.x;       // < B*S*H
    int c = idx & 255;
    int s = (idx >> 8) & (S_ - 1);
    double div = exp((double)(c & ~1) * (-9.210340371976184 / 256.0)); // -ln(1e4)/H
    double arg = (double)s * div;
    float pe = (c & 1) ? (float)cos(arg) : (float)sin(arg);
    g_TR[idx] = tok[idx] + pe;
}

// ---------------- per-span: gather + logits + softmax + pooling -------------
__global__ __launch_bounds__(256) void k_span(const int* __restrict__ span_ids,
                                              const void* __restrict__ maskp) {
    __shared__ float xs[MAXW][H_];     // 16 KB
    __shared__ float qks[NH_][H_];     // 4 KB
    __shared__ float lg[NH_*MAXW];
    __shared__ float attn[NH_][MAXW];

    int sp = blockIdx.x;
    int t  = threadIdx.x;
    int b  = sp >> 13;                 // NS = 8192
    int start = span_ids[2*sp];
    int end   = span_ids[2*sp + 1];
    int msk   = read_mask(maskp, sp);
    int len   = msk ? (end - start) : 0;

    #pragma unroll
    for (int h = 0; h < NH_; h++) qks[h][t] = g_QK[h*H_ + t];

    #pragma unroll
    for (int w = 0; w < MAXW; w++) {
        int pos = min(max(start + w, 0), S_ - 1);
        xs[w][t] = (w < len) ? g_TR[((b << 9) + pos)*H_ + t] : 0.f;
    }
    __syncthreads();

    int wid = t >> 5, lane = t & 31;
    #pragma unroll
    for (int pp = 0; pp < 8; pp++) {            // 8 warps x 8 = 64 (h,w) dots
        int p = wid*8 + pp;
        int h = p >> 4, w = p & 15;
        float s = 0.f;
        #pragma unroll
        for (int c = lane; c < H_; c += 32) s += qks[h][c] * xs[w][c];
        #pragma unroll
        for (int o = 16; o; o >>= 1) s += __shfl_xor_sync(0xFFFFFFFFu, s, o);
        if (lane == 0) lg[p] = s + g_LB[h];
    }
    __syncthreads();

    if (t < NH_) {
        float l[MAXW], m = NEGV;
        #pragma unroll
        for (int w = 0; w < MAXW; w++) { l[w] = (w < len) ? lg[t*MAXW + w] : NEGV; m = fmaxf(m, l[w]); }
        float sum = 0.f;
        #pragma unroll
        for (int w = 0; w < MAXW; w++) { l[w] = expf(l[w] - m); sum += l[w]; }
        float inv = 1.f / sum;
        #pragma unroll
        for (int w = 0; w < MAXW; w++) attn[t][w] = l[w] * inv;
    }
    __syncthreads();

    float a0 = 0.f, a1 = 0.f, a2 = 0.f, a3 = 0.f;
    #pragma unroll
    for (int w = 0; w < MAXW; w++) {
        float xv = xs[w][t];
        a0 += attn[0][w]*xv; a1 += attn[1][w]*xv; a2 += attn[2][w]*xv; a3 += attn[3][w]*xv;
    }
    size_t base = (size_t)sp * (NH_*H_) + t;
    g_XP[base]         = a0;
    g_XP[base +   H_]  = a1;
    g_XP[base + 2*H_]  = a2;
    g_XP[base + 3*H_]  = a3;
}

// ---------------- tiled fp32 GEMM: C = A(MxK) * B(KxN) + epilogue -----------
// EPI 0: +bias[col] ; EPI 1: relu(+bias) ; EPI 2: +bias + resid[row,col]
template<int EPI>
__global__ __launch_bounds__(256, 2)
void k_sgemm(const float* __restrict__ A, const float* __restrict__ Bm,
             float* __restrict__ C, const float* __restrict__ bias,
             const float* __restrict__ resid, int M, int N, int K) {
    __shared__ float As[16][128];
    __shared__ float Bs[16][128];
    const int tid = threadIdx.x;
    const int bx = blockIdx.x, by = blockIdx.y;
    const int tx = tid & 15, ty = tid >> 4;

    const float* Ab = A  + (size_t)by * 128 * K;
    const float* Bb = Bm + (size_t)bx * 128;

    const int ar0 = tid >> 2, akc = tid & 3;   // A: 64 rows per half, 4 float4/row
    const int ar1 = ar0 + 64;
    const int bk0 = tid >> 5, bnc = tid & 31;  // B: 8 rows per half, 32 float4/row
    const int bk1 = bk0 + 8;

    float4 a0, a1, b0, b1;
    a0 = *(const float4*)(Ab + (size_t)ar0*K + akc*4);
    a1 = *(const float4*)(Ab + (size_t)ar1*K + akc*4);
    b0 = *(const float4*)(Bb + (size_t)bk0*N + bnc*4);
    b1 = *(const float4*)(Bb + (size_t)bk1*N + bnc*4);
    As[akc*4+0][ar0]=a0.x; As[akc*4+1][ar0]=a0.y; As[akc*4+2][ar0]=a0.z; As[akc*4+3][ar0]=a0.w;
    As[akc*4+0][ar1]=a1.x; As[akc*4+1][ar1]=a1.y; As[akc*4+2][ar1]=a1.z; As[akc*4+3][ar1]=a1.w;
    *(float4*)&Bs[bk0][bnc*4] = b0;
    *(float4*)&Bs[bk1][bnc*4] = b1;
    __syncthreads();

    float acc[8][8];
    #pragma unroll
    for (int u = 0; u < 8; u++)
        #pragma unroll
        for (int v = 0; v < 8; v++) acc[u][v] = 0.f;

    for (int kb = 0; kb < K; kb += 16) {
        bool has = (kb + 16) < K;
        if (has) {
            a0 = *(const float4*)(Ab + (size_t)ar0*K + kb + 16 + akc*4);
            a1 = *(const float4*)(Ab + (size_t)ar1*K + kb + 16 + akc*4);
            b0 = *(const float4*)(Bb + (size_t)(kb + 16 + bk0)*N + bnc*4);
            b1 = *(const float4*)(Bb + (size_t)(kb + 16 + bk1)*N + bnc*4);
        }
        #pragma unroll
        for (int kk = 0; kk < 16; kk++) {
            float av[8], bv[8];
            #pragma unroll
            for (int u = 0; u < 8; u++) av[u] = As[kk][ty*8 + u];
            #pragma unroll
            for (int v = 0; v < 8; v++) bv[v] = Bs[kk][tx*8 + v];
            #pragma unroll
            for (int u = 0; u < 8; u++)
                #pragma unroll
                for (int v = 0; v < 8; v++) acc[u][v] += av[u] * bv[v];
        }
        __syncthreads();
        if (has) {
            As[akc*4+0][ar0]=a0.x; As[akc*4+1][ar0]=a0.y; As[akc*4+2][ar0]=a0.z; As[akc*4+3][ar0]=a0.w;
            As[akc*4+0][ar1]=a1.x; As[akc*4+1][ar1]=a1.y; As[akc*4+2][ar1]=a1.z; As[akc*4+3][ar1]=a1.w;
            *(float4*)&Bs[bk0][bnc*4] = b0;
            *(float4*)&Bs[bk1][bnc*4] = b1;
            __syncthreads();
        }
    }

    #pragma unroll
    for (int u = 0; u < 8; u++) {
        int row = by*128 + ty*8 + u;
        int col0 = bx*128 + tx*8;
        float* crow = C + (size_t)row*N + col0;
        #pragma unroll
        for (int v = 0; v < 8; v++) {
            float val = acc[u][v] + bias[col0 + v];
            if (EPI == 1) val = fmaxf(val, 0.f);
            if (EPI == 2) val += resid[(size_t)row*N + col0 + v];
            crow[v] = val;
        }
    }
}

// ---------------- warp-per-row LayerNorm (optionally masked output) ---------
__global__ __launch_bounds__(256) void k_ln(const float* __restrict__ X, float* __restrict__ Yo,
                                            const float* __restrict__ g, const float* __restrict__ bb,
                                            const void* __restrict__ maskp, int use_mask) {
    int gw = (blockIdx.x * 256 + threadIdx.x) >> 5;   // row
    int lane = threadIdx.x & 31;
    const float* x = X + (size_t)gw * H_;
    float v[8]; float s = 0.f;
    #pragma unroll
    for (int i = 0; i < 8; i++) { v[i] = x[lane + 32*i]; s += v[i]; }
    #pragma unroll
    for (int o = 16; o; o >>= 1) s += __shfl_xor_sync(0xFFFFFFFFu, s, o);
    float mean = s * (1.f/H_);
    float sv = 0.f;
    #pragma unroll
    for (int i = 0; i < 8; i++) { float d = v[i] - mean; sv += d*d; }
    #pragma unroll
    for (int o = 16; o; o >>= 1) sv += __shfl_xor_sync(0xFFFFFFFFu, sv, o);
    float inv = rsqrtf(sv * (1.f/H_) + 1e-5f);
    float mf = 1.f;
    if (use_mask) mf = read_mask(maskp, gw) ? 1.f : 0.f;
    float* y = Yo + (size_t)gw * H_;
    #pragma unroll
    for (int i = 0; i < 8; i++) {
        int c = lane + 32*i;
        y[c] = ((v[i] - mean) * inv * g[c] + bb[c]) * mf;
    }
}

// ---------------- launch --------------------------------------------------
extern "C" void kernel_launch(void* const* d_in, const int* in_sizes, int n_in,
                              void* d_out, int out_size) {
    const float* tok   = (const float*)d_in[0];
    const int*   sids  = (const int*)  d_in[1];
    const void*  masks =               d_in[2];
    // d_in[3] = pooling (unused by reference)
    const float* dq    = (const float*)d_in[4];
    const float* wq    = (const float*)d_in[5];
    const float* wk    = (const float*)d_in[6];
    const float* wv    = (const float*)d_in[7];
    const float* bqkv  = (const float*)d_in[8];
    const float* wo    = (const float*)d_in[9];
    const float* bo    = (const float*)d_in[10];
    const float* lng   = (const float*)d_in[11];
    const float* lnb   = (const float*)d_in[12];
    const float* w1    = (const float*)d_in[13];
    const float* b1    = (const float*)d_in[14];
    const float* w2    = (const float*)d_in[15];
    const float* b2    = (const float*)d_in[16];
    float* out = (float*)d_out;

    float *TR, *XP, *Mm, *T1, *Y, *F, *BO;
    cudaGetSymbolAddress((void**)&TR, g_TR);
    cudaGetSymbolAddress((void**)&XP, g_XP);
    cudaGetSymbolAddress((void**)&Mm, g_M);
    cudaGetSymbolAddress((void**)&T1, g_T1);
    cudaGetSymbolAddress((void**)&Y,  g_Y);
    cudaGetSymbolAddress((void**)&F,  g_F);
    cudaGetSymbolAddress((void**)&BO, g_BO);

    k_detect_mask<<<1, 256>>>((const unsigned int*)masks);
    k_precompute<<<1, 256>>>(dq, wq, wk, bqkv, wo, bo);
    k_buildM<<<NH_*H_, 256>>>(wv, wo);
    k_addpe<<<(B_*S_*H_)/256, 256>>>(tok);
    k_span<<<NSPAN, 256>>>(sids, masks);

    // out1 = XP @ M + BO            (32768 x 256, K=1024)
    k_sgemm<0><<<dim3(H_/128, NSPAN/128), 256>>>(XP, Mm, T1, BO, nullptr, NSPAN, H_, NH_*H_);
    // y = LN(out1)
    k_ln<<<NSPAN/8, 256>>>(T1, Y, lng, lnb, nullptr, 0);
    // f_hid = relu(y @ w1 + b1)     (32768 x 1024, K=256)
    k_sgemm<1><<<dim3(FF_/128, NSPAN/128), 256>>>(Y, w1, F, b1, nullptr, NSPAN, FF_, H_);
    // out2 = f_hid @ w2 + b2 + y    (32768 x 256, K=1024)
    k_sgemm<2><<<dim3(H_/128, NSPAN/128), 256>>>(F, w2, T1, b2, Y, NSPAN, H_, FF_);
    // out = LN(out2) * mask
    k_ln<<<NSPAN/8, 256>>>(T1, out, lng, lnb, masks, 1);
}

// round 3
// speedup vs baseline: 1.9974x; 1.9974x over previous
#include <cuda_runtime.h>
#include <cuda_bf16.h>
#include <cstdint>
#include <math.h>

// ================= problem constants =================
#define B_    4
#define S_    512
#define NS_   8192
#define MAXW  16
#define H_    256
#define NH_   4
#define DH_   64
#define FF_   1024
#define NSPAN (B_*NS_)          // 32768
#define NEGV  (-1000000000.0f)

// ================= device scratch =================
__device__ float g_TR[B_*S_*H_];
__device__ float g_QK[NH_*H_];
__device__ float g_LB[NH_];
__device__ float g_BO[H_];
__device__ float g_T1[(size_t)NSPAN*H_];                 // GEMM1/GEMM3 fp32 out
__device__ __nv_bfloat16 g_XPh[(size_t)NSPAN*NH_*H_];    // 64 MB
__device__ __nv_bfloat16 g_XPl[(size_t)NSPAN*NH_*H_];
__device__ __nv_bfloat16 g_Yh[(size_t)NSPAN*H_];
__device__ __nv_bfloat16 g_Yl[(size_t)NSPAN*H_];
__device__ __nv_bfloat16 g_Fh[(size_t)NSPAN*FF_];
__device__ __nv_bfloat16 g_Fl[(size_t)NSPAN*FF_];
__device__ __nv_bfloat16 g_MTh[H_*NH_*H_];               // [256][1024]
__device__ __nv_bfloat16 g_MTl[H_*NH_*H_];
__device__ __nv_bfloat16 g_W1Th[FF_*H_];                 // [1024][256]
__device__ __nv_bfloat16 g_W1Tl[FF_*H_];
__device__ __nv_bfloat16 g_W2Th[H_*FF_];                 // [256][1024]
__device__ __nv_bfloat16 g_W2Tl[H_*FF_];
__device__ int g_mask_is_byte;

__device__ __forceinline__ void split_bf16(float x, __nv_bfloat16& h, __nv_bfloat16& l) {
    h = __float2bfloat16(x);
    l = __float2bfloat16(x - __bfloat162float(h));
}

// ================= small PTX helpers (all arch-portable, no tcgen05) ========
__device__ __forceinline__ uint32_t smem_u32(const void* p) {
    uint32_t a;
    asm("{ .reg .u64 t; cvta.to.shared.u64 t, %1; cvt.u32.u64 %0, t; }" : "=r"(a) : "l"(p));
    return a;
}
__device__ __forceinline__ void cp16(uint32_t s, const void* g) {
    asm volatile("cp.async.cg.shared.global [%0], [%1], 16;" :: "r"(s), "l"(g));
}
#define CP_COMMIT() asm volatile("cp.async.commit_group;" ::: "memory")
#define CP_WAIT(n)  asm volatile("cp.async.wait_group %0;" :: "n"(n) : "memory")

__device__ __forceinline__ void ldsm4(uint32_t& r0, uint32_t& r1, uint32_t& r2, uint32_t& r3, uint32_t a) {
    asm volatile("ldmatrix.sync.aligned.m8n8.x4.shared.b16 {%0,%1,%2,%3}, [%4];"
                 : "=r"(r0), "=r"(r1), "=r"(r2), "=r"(r3) : "r"(a));
}
__device__ __forceinline__ void mma16816(float* d, uint32_t a0, uint32_t a1, uint32_t a2, uint32_t a3,
                                         uint32_t b0, uint32_t b1) {
    asm volatile("mma.sync.aligned.m16n8k16.row.col.f32.bf16.bf16.f32 "
                 "{%0,%1,%2,%3}, {%4,%5,%6,%7}, {%8,%9}, {%0,%1,%2,%3};"
                 : "+f"(d[0]), "+f"(d[1]), "+f"(d[2]), "+f"(d[3])
                 : "r"(a0), "r"(a1), "r"(a2), "r"(a3), "r"(b0), "r"(b1));
}

// ================= mask format detection =================
__global__ void k_detect_mask(const unsigned int* __restrict__ m) {
    __shared__ int found;
    if (threadIdx.x == 0) found = 0;
    __syncthreads();
    unsigned v = m[threadIdx.x];
    if (v > 1u) atomicOr(&found, 1);
    __syncthreads();
    if (threadIdx.x == 0) g_mask_is_byte = found;
}
__device__ __forceinline__ int read_mask(const void* p, int i) {
    if (g_mask_is_byte) return ((const unsigned char*)p)[i] != 0;
    return ((const int*)p)[i] != 0;
}

// ================= precompute: qk, logit bias, output bias =================
__global__ void k_precompute(const float* __restrict__ dq, const float* __restrict__ wq,
                             const float* __restrict__ wk, const float* __restrict__ bqkv,
                             const float* __restrict__ wo, const float* __restrict__ bo) {
    __shared__ float qs[H_];
    int t = threadIdx.x;
    float s = bqkv[t];
    for (int c = 0; c < H_; c++) s += dq[c] * wq[t*H_ + c];
    qs[t] = s;
    __syncthreads();
    #pragma unroll
    for (int h = 0; h < NH_; h++) {
        float acc = 0.f;
        for (int d = 0; d < DH_; d++) acc += qs[h*DH_ + d] * wk[(h*DH_ + d)*H_ + t];
        g_QK[h*H_ + t] = 0.125f * acc;
    }
    if (t < NH_) {
        float acc = 0.f;
        for (int d = 0; d < DH_; d++) acc += qs[t*DH_ + d] * bqkv[H_ + t*DH_ + d];
        g_LB[t] = 0.125f * acc;
    }
    float bacc = bo[t] + dq[t];
    for (int i = 0; i < H_; i++) bacc += bqkv[2*H_ + i] * wo[t*H_ + i];
    g_BO[t] = bacc;
}

// ===== MT[j][k] (j<256 rows, k=h*256+c) = sum_d w_v[h*64+d][c] * w_o[j][h*64+d] =====
__global__ void k_buildM(const float* __restrict__ wv, const float* __restrict__ wo) {
    __shared__ float wvs[DH_];
    int bid = blockIdx.x;                // k index: h*256 + c
    int h = bid >> 8, c = bid & 255;
    int t = threadIdx.x;                 // j
    if (t < DH_) wvs[t] = wv[(h*DH_ + t)*H_ + c];
    __syncthreads();
    float acc = 0.f;
    #pragma unroll 8
    for (int d = 0; d < DH_; d++) acc += wvs[d] * wo[t*H_ + h*DH_ + d];
    __nv_bfloat16 hh, ll; split_bf16(acc, hh, ll);
    g_MTh[(size_t)t*(NH_*H_) + bid] = hh;
    g_MTl[(size_t)t*(NH_*H_) + bid] = ll;
}

// ===== transpose + split: src[R][C] fp32 -> dst[C][R] bf16 hi/lo =====
__global__ void k_tsplit(const float* __restrict__ src, __nv_bfloat16* __restrict__ dh,
                         __nv_bfloat16* __restrict__ dl, int R, int C) {
    int o = blockIdx.x * 256 + threadIdx.x;       // o = n*R + k
    int n = o / R, k = o - n*R;
    float v = src[(size_t)k*C + n];
    __nv_bfloat16 hh, ll; split_bf16(v, hh, ll);
    dh[o] = hh; dl[o] = ll;
}

// ================= token_reps + positional encoding =================
__global__ void k_addpe(const float* __restrict__ tok) {
    int idx = blockIdx.x * 256 + threadIdx.x;
    int c = idx & 255;
    int s = (idx >> 8) & (S_ - 1);
    double div = exp((double)(c & ~1) * (-9.210340371976184 / 256.0));
    double arg = (double)s * div;
    float pe = (c & 1) ? (float)cos(arg) : (float)sin(arg);
    g_TR[idx] = tok[idx] + pe;
}

// ================= per-span gather + logits + softmax + pooling =================
__global__ __launch_bounds__(256) void k_span(const int* __restrict__ span_ids,
                                              const void* __restrict__ maskp) {
    __shared__ float xs[MAXW][H_];
    __shared__ float qks[NH_][H_];
    __shared__ float lg[NH_*MAXW];
    __shared__ float attn[NH_][MAXW];

    int sp = blockIdx.x;
    int t  = threadIdx.x;
    int b  = sp >> 13;
    int start = span_ids[2*sp];
    int end   = span_ids[2*sp + 1];
    int msk   = read_mask(maskp, sp);
    int len   = msk ? (end - start) : 0;

    #pragma unroll
    for (int h = 0; h < NH_; h++) qks[h][t] = g_QK[h*H_ + t];
    #pragma unroll
    for (int w = 0; w < MAXW; w++) {
        int pos = min(max(start + w, 0), S_ - 1);
        xs[w][t] = (w < len) ? g_TR[((b << 9) + pos)*H_ + t] : 0.f;
    }
    __syncthreads();

    int wid = t >> 5, lane = t & 31;
    #pragma unroll
    for (int pp = 0; pp < 8; pp++) {
        int p = wid*8 + pp;
        int h = p >> 4, w = p & 15;
        float s = 0.f;
        #pragma unroll
        for (int c = lane; c < H_; c += 32) s += qks[h][c] * xs[w][c];
        #pragma unroll
        for (int o = 16; o; o >>= 1) s += __shfl_xor_sync(0xFFFFFFFFu, s, o);
        if (lane == 0) lg[p] = s + g_LB[h];
    }
    __syncthreads();

    if (t < NH_) {
        float l[MAXW], m = NEGV;
        #pragma unroll
        for (int w = 0; w < MAXW; w++) { l[w] = (w < len) ? lg[t*MAXW + w] : NEGV; m = fmaxf(m, l[w]); }
        float sum = 0.f;
        #pragma unroll
        for (int w = 0; w < MAXW; w++) { l[w] = expf(l[w] - m); sum += l[w]; }
        float inv = 1.f / sum;
        #pragma unroll
        for (int w = 0; w < MAXW; w++) attn[t][w] = l[w] * inv;
    }
    __syncthreads();

    float a[NH_] = {0.f, 0.f, 0.f, 0.f};
    #pragma unroll
    for (int w = 0; w < MAXW; w++) {
        float xv = xs[w][t];
        #pragma unroll
        for (int h = 0; h < NH_; h++) a[h] += attn[h][w]*xv;
    }
    size_t base = (size_t)sp * (NH_*H_) + t;
    #pragma unroll
    for (int h = 0; h < NH_; h++) {
        __nv_bfloat16 hh, ll; split_bf16(a[h], hh, ll);
        g_XPh[base + h*H_] = hh;
        g_XPl[base + h*H_] = ll;
    }
}

// ================= mma.sync bf16 GEMM, 3-term compensated ====================
// C(MxN) = (Ah+Al)(MxK) @ (Bh+Bl)(NxK)^T  ~=  Ah@Bh + Ah@Bl + Al@Bh
// EPI 0: C = D + bias[col]                 (fp32)
// EPI 1: relu(D + bias) -> bf16 hi/lo (Oh/Ol)
// EPI 2: C = D + bias + (Rh+Rl)[row,col]   (fp32)
//
// CTA tile 128x128, K-chunk 32, 2-stage cp.async pipeline.
// SMEM per stage (bf16 elems, rows padded to 40): Ahi | Alo | Bhi | Blo, 5120 each.
#define PADK     40
#define MATSZ    (128*PADK)           // 5120 elems
#define STAGESZ  (4*MATSZ)            // 20480 elems = 40960 B
#define GSMEM_BYTES (2*STAGESZ*2)     // 81920 B

__device__ __forceinline__ void stage_load(uint32_t sbase, int stg,
        const __nv_bfloat16* __restrict__ Ah, const __nv_bfloat16* __restrict__ Al,
        const __nv_bfloat16* __restrict__ Bh, const __nv_bfloat16* __restrict__ Bl,
        int row0, int col0, int K, int kb, int tid) {
    uint32_t sb = sbase + stg*(STAGESZ*2);
    const __nv_bfloat16* P[4] = {Ah, Al, Bh, Bl};
    #pragma unroll
    for (int m = 0; m < 4; m++) {
        int r0 = (m < 2) ? row0 : col0;
        const __nv_bfloat16* p = P[m];
        #pragma unroll
        for (int half = 0; half < 2; half++) {
            int idx = tid + (half << 8);
            int row = idx >> 2, kc = idx & 3;
            cp16(sb + m*(MATSZ*2) + row*(PADK*2) + kc*16,
                 p + (size_t)(r0 + row)*K + kb + kc*8);
        }
    }
    CP_COMMIT();
}

template<int EPI>
__global__ __launch_bounds__(256, 2)
void k_gemm(const __nv_bfloat16* __restrict__ Ah, const __nv_bfloat16* __restrict__ Al,
            const __nv_bfloat16* __restrict__ Bh, const __nv_bfloat16* __restrict__ Bl,
            const float* __restrict__ bias, float* __restrict__ C,
            __nv_bfloat16* __restrict__ Oh, __nv_bfloat16* __restrict__ Ol,
            const __nv_bfloat16* __restrict__ Rh, const __nv_bfloat16* __restrict__ Rl,
            int K, int N) {
    extern __shared__ __nv_bfloat16 smem[];
    uint32_t sbase = smem_u32(smem);
    const int tid = threadIdx.x, wid = tid >> 5, lane = tid & 31;
    const int row0 = blockIdx.y * 128, col0 = blockIdx.x * 128;
    const int wm = (wid >> 2) * 64;          // warp row offset in tile
    const int wn = (wid & 3) * 32;           // warp col offset in tile
    const int NSTG = K >> 5;

    // per-thread ldmatrix byte offsets (within a matrix)
    const uint32_t aoff = ((lane & 15) * PADK + ((lane >> 4) << 3)) * 2;
    const uint32_t boff = (((((lane >> 4) << 3) + (lane & 7)) * PADK) + (((lane >> 3) & 1) << 3)) * 2;

    float acc[4][4][4];
    #pragma unroll
    for (int mi = 0; mi < 4; mi++)
        #pragma unroll
        for (int ni = 0; ni < 4; ni++)
            #pragma unroll
            for (int e = 0; e < 4; e++) acc[mi][ni][e] = 0.f;

    stage_load(sbase, 0, Ah, Al, Bh, Bl, row0, col0, K, 0, tid);
    if (NSTG > 1) stage_load(sbase, 1, Ah, Al, Bh, Bl, row0, col0, K, 32, tid);
    else          CP_COMMIT();

    for (int s = 0; s < NSTG; s++) {
        if (s == NSTG - 1) { CP_WAIT(0); } else { CP_WAIT(1); }
        __syncthreads();
        uint32_t sb = sbase + (s & 1)*(STAGESZ*2);
        uint32_t sAh = sb,                sAl = sb + MATSZ*2;
        uint32_t sBh = sb + 2*MATSZ*2,    sBl = sb + 3*MATSZ*2;

        #pragma unroll
        for (int kk = 0; kk < 2; kk++) {
            uint32_t kby = kk * 32;      // 16 elems * 2B
            uint32_t a[4][4], bh[4][2], bl[4][2];
            // A hi fragments
            #pragma unroll
            for (int mi = 0; mi < 4; mi++)
                ldsm4(a[mi][0], a[mi][1], a[mi][2], a[mi][3],
                      sAh + aoff + (wm + mi*16)*(PADK*2) + kby);
            // B hi fragments (x4 covers two n8 tiles)
            #pragma unroll
            for (int nj = 0; nj < 2; nj++)
                ldsm4(bh[2*nj][0], bh[2*nj][1], bh[2*nj+1][0], bh[2*nj+1][1],
                      sBh + boff + (wn + nj*16)*(PADK*2) + kby);
            #pragma unroll
            for (int mi = 0; mi < 4; mi++)
                #pragma unroll
                for (int ni = 0; ni < 4; ni++)
                    mma16816(acc[mi][ni], a[mi][0], a[mi][1], a[mi][2], a[mi][3],
                             bh[ni][0], bh[ni][1]);
            // B lo fragments, reuse A hi
            #pragma unroll
            for (int nj = 0; nj < 2; nj++)
                ldsm4(bl[2*nj][0], bl[2*nj][1], bl[2*nj+1][0], bl[2*nj+1][1],
                      sBl + boff + (wn + nj*16)*(PADK*2) + kby);
            #pragma unroll
            for (int mi = 0; mi < 4; mi++)
                #pragma unroll
                for (int ni = 0; ni < 4; ni++)
                    mma16816(acc[mi][ni], a[mi][0], a[mi][1], a[mi][2], a[mi][3],
                             bl[ni][0], bl[ni][1]);
            // A lo fragments (overwrite), with B hi
            #pragma unroll
            for (int mi = 0; mi < 4; mi++)
                ldsm4(a[mi][0], a[mi][1], a[mi][2], a[mi][3],
                      sAl + aoff + (wm + mi*16)*(PADK*2) + kby);
            #pragma unroll
            for (int mi = 0; mi < 4; mi++)
                #pragma unroll
                for (int ni = 0; ni < 4; ni++)
                    mma16816(acc[mi][ni], a[mi][0], a[mi][1], a[mi][2], a[mi][3],
                             bh[ni][0], bh[ni][1]);
        }
        __syncthreads();
        if (s + 2 < NSTG)
            stage_load(sbase, s & 1, Ah, Al, Bh, Bl, row0, col0, K, (s + 2) << 5, tid);
    }

    // ---- epilogue: fragments -> gmem ----
    #pragma unroll
    for (int mi = 0; mi < 4; mi++) {
        #pragma unroll
        for (int ni = 0; ni < 4; ni++) {
            int gr0 = row0 + wm + mi*16 + (lane >> 2);
            int gc  = col0 + wn + ni*8 + ((lane & 3) << 1);
            float b0 = bias[gc], b1 = bias[gc + 1];
            float v00 = acc[mi][ni][0] + b0, v01 = acc[mi][ni][1] + b1;
            float v10 = acc[mi][ni][2] + b0, v11 = acc[mi][ni][3] + b1;
            if (EPI == 0) {
                *(float2*)(C + (size_t)gr0*N + gc)       = make_float2(v00, v01);
                *(float2*)(C + (size_t)(gr0+8)*N + gc)   = make_float2(v10, v11);
            } else if (EPI == 1) {
                union { __nv_bfloat16 b[2]; uint32_t u; } h0, l0, h1, l1;
                float w00 = fmaxf(v00, 0.f), w01 = fmaxf(v01, 0.f);
                float w10 = fmaxf(v10, 0.f), w11 = fmaxf(v11, 0.f);
                split_bf16(w00, h0.b[0], l0.b[0]); split_bf16(w01, h0.b[1], l0.b[1]);
                split_bf16(w10, h1.b[0], l1.b[0]); split_bf16(w11, h1.b[1], l1.b[1]);
                *(uint32_t*)(Oh + (size_t)gr0*N + gc)     = h0.u;
                *(uint32_t*)(Ol + (size_t)gr0*N + gc)     = l0.u;
                *(uint32_t*)(Oh + (size_t)(gr0+8)*N + gc) = h1.u;
                *(uint32_t*)(Ol + (size_t)(gr0+8)*N + gc) = l1.u;
            } else {
                union { __nv_bfloat16 b[2]; uint32_t u; } rh0, rl0, rh1, rl1;
                rh0.u = *(const uint32_t*)(Rh + (size_t)gr0*N + gc);
                rl0.u = *(const uint32_t*)(Rl + (size_t)gr0*N + gc);
                rh1.u = *(const uint32_t*)(Rh + (size_t)(gr0+8)*N + gc);
                rl1.u = *(const uint32_t*)(Rl + (size_t)(gr0+8)*N + gc);
                v00 += __bfloat162float(rh0.b[0]) + __bfloat162float(rl0.b[0]);
                v01 += __bfloat162float(rh0.b[1]) + __bfloat162float(rl0.b[1]);
                v10 += __bfloat162float(rh1.b[0]) + __bfloat162float(rl1.b[0]);
                v11 += __bfloat162float(rh1.b[1]) + __bfloat162float(rl1.b[1]);
                *(float2*)(C + (size_t)gr0*N + gc)       = make_float2(v00, v01);
                *(float2*)(C + (size_t)(gr0+8)*N + gc)   = make_float2(v10, v11);
            }
        }
    }
}

// ================= LayerNorm variants =================
__global__ __launch_bounds__(256) void k_ln_bf16(const float* __restrict__ X,
        __nv_bfloat16* __restrict__ Yh, __nv_bfloat16* __restrict__ Yl,
        const float* __restrict__ g, const float* __restrict__ bb) {
    int gw = (blockIdx.x * 256 + threadIdx.x) >> 5;
    int lane = threadIdx.x & 31;
    const float* x = X + (size_t)gw * H_;
    float v[8]; float s = 0.f;
    #pragma unroll
    for (int i = 0; i < 8; i++) { v[i] = x[lane + 32*i]; s += v[i]; }
    #pragma unroll
    for (int o = 16; o; o >>= 1) s += __shfl_xor_sync(0xFFFFFFFFu, s, o);
    float mean = s * (1.f/H_);
    float sv = 0.f;
    #pragma unroll
    for (int i = 0; i < 8; i++) { float d = v[i] - mean; sv += d*d; }
    #pragma unroll
    for (int o = 16; o; o >>= 1) sv += __shfl_xor_sync(0xFFFFFFFFu, sv, o);
    float inv = rsqrtf(sv * (1.f/H_) + 1e-5f);
    #pragma unroll
    for (int i = 0; i < 8; i++) {
        int c = lane + 32*i;
        float yv = (v[i] - mean) * inv * g[c] + bb[c];
        __nv_bfloat16 hh, ll; split_bf16(yv, hh, ll);
        Yh[(size_t)gw*H_ + c] = hh;
        Yl[(size_t)gw*H_ + c] = ll;
    }
}

__global__ __launch_bounds__(256) void k_ln_final(const float* __restrict__ X, float* __restrict__ Yo,
        const float* __restrict__ g, const float* __restrict__ bb, const void* __restrict__ maskp) {
    int gw = (blockIdx.x * 256 + threadIdx.x) >> 5;
    int lane = threadIdx.x & 31;
    const float* x = X + (size_t)gw * H_;
    float v[8]; float s = 0.f;
    #pragma unroll
    for (int i = 0; i < 8; i++) { v[i] = x[lane + 32*i]; s += v[i]; }
    #pragma unroll
    for (int o = 16; o; o >>= 1) s += __shfl_xor_sync(0xFFFFFFFFu, s, o);
    float mean = s * (1.f/H_);
    float sv = 0.f;
    #pragma unroll
    for (int i = 0; i < 8; i++) { float d = v[i] - mean; sv += d*d; }
    #pragma unroll
    for (int o = 16; o; o >>= 1) sv += __shfl_xor_sync(0xFFFFFFFFu, sv, o);
    float inv = rsqrtf(sv * (1.f/H_) + 1e-5f);
    float mf = read_mask(maskp, gw) ? 1.f : 0.f;
    float* y = Yo + (size_t)gw * H_;
    #pragma unroll
    for (int i = 0; i < 8; i++) {
        int c = lane + 32*i;
        y[c] = ((v[i] - mean) * inv * g[c] + bb[c]) * mf;
    }
}

// ================= launch =================
extern "C" void kernel_launch(void* const* d_in, const int* in_sizes, int n_in,
                              void* d_out, int out_size) {
    const float* tok   = (const float*)d_in[0];
    const int*   sids  = (const int*)  d_in[1];
    const void*  masks =               d_in[2];
    const float* dq    = (const float*)d_in[4];
    const float* wq    = (const float*)d_in[5];
    const float* wk    = (const float*)d_in[6];
    const float* wv    = (const float*)d_in[7];
    const float* bqkv  = (const float*)d_in[8];
    const float* wo    = (const float*)d_in[9];
    const float* bo    = (const float*)d_in[10];
    const float* lng   = (const float*)d_in[11];
    const float* lnb   = (const float*)d_in[12];
    const float* w1    = (const float*)d_in[13];
    const float* b1    = (const float*)d_in[14];
    const float* w2    = (const float*)d_in[15];
    const float* b2    = (const float*)d_in[16];
    float* out = (float*)d_out;

    float *T1, *BO;
    __nv_bfloat16 *XPh, *XPl, *Yh, *Yl, *Fh, *Fl, *MTh, *MTl, *W1Th, *W1Tl, *W2Th, *W2Tl;
    cudaGetSymbolAddress((void**)&T1,  g_T1);
    cudaGetSymbolAddress((void**)&BO,  g_BO);
    cudaGetSymbolAddress((void**)&XPh, g_XPh);
    cudaGetSymbolAddress((void**)&XPl, g_XPl);
    cudaGetSymbolAddress((void**)&Yh,  g_Yh);
    cudaGetSymbolAddress((void**)&Yl,  g_Yl);
    cudaGetSymbolAddress((void**)&Fh,  g_Fh);
    cudaGetSymbolAddress((void**)&Fl,  g_Fl);
    cudaGetSymbolAddress((void**)&MTh, g_MTh);
    cudaGetSymbolAddress((void**)&MTl, g_MTl);
    cudaGetSymbolAddress((void**)&W1Th, g_W1Th);
    cudaGetSymbolAddress((void**)&W1Tl, g_W1Tl);
    cudaGetSymbolAddress((void**)&W2Th, g_W2Th);
    cudaGetSymbolAddress((void**)&W2Tl, g_W2Tl);

    cudaFuncSetAttribute(k_gemm<0>, cudaFuncAttributeMaxDynamicSharedMemorySize, GSMEM_BYTES);
    cudaFuncSetAttribute(k_gemm<1>, cudaFuncAttributeMaxDynamicSharedMemorySize, GSMEM_BYTES);
    cudaFuncSetAttribute(k_gemm<2>, cudaFuncAttributeMaxDynamicSharedMemorySize, GSMEM_BYTES);

    k_detect_mask<<<1, 256>>>((const unsigned int*)masks);
    k_precompute<<<1, 256>>>(dq, wq, wk, bqkv, wo, bo);
    k_buildM<<<NH_*H_, 256>>>(wv, wo);
    k_tsplit<<<(FF_*H_)/256, 256>>>(w1, W1Th, W1Tl, H_, FF_);   // [256][1024] -> [1024][256]
    k_tsplit<<<(FF_*H_)/256, 256>>>(w2, W2Th, W2Tl, FF_, H_);   // [1024][256] -> [256][1024]
    k_addpe<<<(B_*S_*H_)/256, 256>>>(tok);
    k_span<<<NSPAN, 256>>>(sids, masks);

    // GEMM1: T1 = XP(32768x1024) @ MT^T (N=256) + BO
    k_gemm<0><<<dim3(2, NSPAN/128), 256, GSMEM_BYTES>>>(XPh, XPl, MTh, MTl, BO, T1,
                                                        nullptr, nullptr, nullptr, nullptr, NH_*H_, H_);
    // Y = LN(T1) -> bf16 hi/lo
    k_ln_bf16<<<NSPAN/8, 256>>>(T1, Yh, Yl, lng, lnb);
    // GEMM2: F = relu(Y(32768x256) @ W1T^T (N=1024) + b1) -> bf16 hi/lo
    k_gemm<1><<<dim3(8, NSPAN/128), 256, GSMEM_BYTES>>>(Yh, Yl, W1Th, W1Tl, b1, nullptr,
                                                        Fh, Fl, nullptr, nullptr, H_, FF_);
    // GEMM3: T1 = F(32768x1024) @ W2T^T (N=256) + b2 + Y
    k_gemm<2><<<dim3(2, NSPAN/128), 256, GSMEM_BYTES>>>(Fh, Fl, W2Th, W2Tl, b2, T1,
                                                        nullptr, nullptr, Yh, Yl, FF_, H_);
    // out = LN(T1) * mask
    k_ln_final<<<NSPAN/8, 256>>>(T1, out, lng, lnb, masks);
}

// round 6
// speedup vs baseline: 2.8477x; 1.4257x over previous
#include <cuda_runtime.h>
#include <cuda_bf16.h>
#include <cstdint>
#include <math.h>

// ================= problem constants =================
#define B_    4
#define S_    512
#define NS_   8192
#define MAXW  16
#define H_    256
#define NH_   4
#define DH_   64
#define FF_   1024
#define NSPAN (B_*NS_)          // 32768
#define NEGV  (-1000000000.0f)

// ================= device scratch =================
__device__ float g_TR[B_*S_*H_];
__device__ float g_QK[NH_*H_];
__device__ float g_BO[H_];
__device__ float g_Vtok[B_*S_*H_];               // TR @ w_v^T  (2 MB)
__device__ float4 g_Ltok[B_*S_];                 // per-token logits (4 heads)
__device__ float g_T1[(size_t)NSPAN*H_];
__device__ __nv_bfloat16 g_Ctxh[(size_t)NSPAN*H_];
__device__ __nv_bfloat16 g_Ctxl[(size_t)NSPAN*H_];
__device__ __nv_bfloat16 g_Yh[(size_t)NSPAN*H_];
__device__ __nv_bfloat16 g_Yl[(size_t)NSPAN*H_];
__device__ __nv_bfloat16 g_Fh[(size_t)NSPAN*FF_];
__device__ __nv_bfloat16 g_Fl[(size_t)NSPAN*FF_];
__device__ __nv_bfloat16 g_WOh[H_*H_];           // w_o split, [n][k] (no transpose)
__device__ __nv_bfloat16 g_WOl[H_*H_];
__device__ __nv_bfloat16 g_W1Th[FF_*H_];         // w1^T split  [1024][256]
__device__ __nv_bfloat16 g_W1Tl[FF_*H_];
__device__ __nv_bfloat16 g_W2Th[H_*FF_];         // w2^T split  [256][1024]
__device__ __nv_bfloat16 g_W2Tl[H_*FF_];
__device__ int g_mask_is_byte;

__device__ __forceinline__ void split_bf16(float x, __nv_bfloat16& h, __nv_bfloat16& l) {
    h = __float2bfloat16(x);
    l = __float2bfloat16(x - __bfloat162float(h));
}

// ================= small PTX helpers =================
__device__ __forceinline__ uint32_t smem_u32(const void* p) {
    uint32_t a;
    asm("{ .reg .u64 t; cvta.to.shared.u64 t, %1; cvt.u32.u64 %0, t; }" : "=r"(a) : "l"(p));
    return a;
}
__device__ __forceinline__ void cp16(uint32_t s, const void* g) {
    asm volatile("cp.async.cg.shared.global [%0], [%1], 16;" :: "r"(s), "l"(g));
}
#define CP_COMMIT() asm volatile("cp.async.commit_group;" ::: "memory")
#define CP_WAIT(n)  asm volatile("cp.async.wait_group %0;" :: "n"(n) : "memory")

__device__ __forceinline__ void ldsm4(uint32_t& r0, uint32_t& r1, uint32_t& r2, uint32_t& r3, uint32_t a) {
    asm volatile("ldmatrix.sync.aligned.m8n8.x4.shared.b16 {%0,%1,%2,%3}, [%4];"
                 : "=r"(r0), "=r"(r1), "=r"(r2), "=r"(r3) : "r"(a));
}
__device__ __forceinline__ void mma16816(float* d, uint32_t a0, uint32_t a1, uint32_t a2, uint32_t a3,
                                         uint32_t b0, uint32_t b1) {
    asm volatile("mma.sync.aligned.m16n8k16.row.col.f32.bf16.bf16.f32 "
                 "{%0,%1,%2,%3}, {%4,%5,%6,%7}, {%8,%9}, {%0,%1,%2,%3};"
                 : "+f"(d[0]), "+f"(d[1]), "+f"(d[2]), "+f"(d[3])
                 : "r"(a0), "r"(a1), "r"(a2), "r"(a3), "r"(b0), "r"(b1));
}

// ================= mask format detection =================
__global__ void k_detect_mask(const unsigned int* __restrict__ m) {
    __shared__ int found;
    if (threadIdx.x == 0) found = 0;
    __syncthreads();
    unsigned v = m[threadIdx.x];
    if (v > 1u) atomicOr(&found, 1);
    __syncthreads();
    if (threadIdx.x == 0) g_mask_is_byte = found;
}
__device__ __forceinline__ int read_mask(const void* p, int i) {
    if (g_mask_is_byte) return ((const unsigned char*)p)[i] != 0;
    return ((const int*)p)[i] != 0;
}

// ================= token_reps + positional encoding =================
__global__ void k_addpe(const float* __restrict__ tok) {
    int idx = blockIdx.x * 256 + threadIdx.x;
    int c = idx & 255;
    int s = (idx >> 8) & (S_ - 1);
    double div = exp((double)(c & ~1) * (-9.210340371976184 / 256.0));
    double arg = (double)s * div;
    float pe = (c & 1) ? (float)cos(arg) : (float)sin(arg);
    g_TR[idx] = tok[idx] + pe;
}

// ================= precompute: qk (scaled), output bias =================
__global__ void k_precompute(const float* __restrict__ dq, const float* __restrict__ wq,
                             const float* __restrict__ wk, const float* __restrict__ bqkv,
                             const float* __restrict__ wo, const float* __restrict__ bo) {
    __shared__ float qs[H_];
    int t = threadIdx.x;
    float s = bqkv[t];
    for (int c = 0; c < H_; c++) s += dq[c] * wq[t*H_ + c];
    qs[t] = s;
    __syncthreads();
    #pragma unroll
    for (int h = 0; h < NH_; h++) {
        float acc = 0.f;
        for (int d = 0; d < DH_; d++) acc += qs[h*DH_ + d] * wk[(h*DH_ + d)*H_ + t];
        g_QK[h*H_ + t] = 0.125f * acc;
    }
    float bacc = bo[t] + dq[t];
    for (int i = 0; i < H_; i++) bacc += bqkv[2*H_ + i] * wo[t*H_ + i];
    g_BO[t] = bacc;
}

// ===== V_tok[t][c] = sum_k TR[t][k] * w_v[c][k]   (8 tokens per block) =====
__global__ __launch_bounds__(256) void k_vtok(const float* __restrict__ wv) {
    __shared__ float xs[8][H_];
    int t0 = blockIdx.x * 8;
    int tid = threadIdx.x;
    #pragma unroll
    for (int r = 0; r < 8; r++) xs[r][tid] = g_TR[(t0 + r)*H_ + tid];
    __syncthreads();
    float acc[8] = {0,0,0,0,0,0,0,0};
    const float* wr = wv + (size_t)tid*H_;
    for (int k = 0; k < H_; k++) {
        float w = wr[k];
        #pragma unroll
        for (int r = 0; r < 8; r++) acc[r] += xs[r][k] * w;
    }
    #pragma unroll
    for (int r = 0; r < 8; r++) g_Vtok[(t0 + r)*H_ + tid] = acc[r];
}

// ===== L_tok[t] = (qk_h . TR[t]) for 4 heads; one warp per token =====
__global__ __launch_bounds__(256) void k_ltok() {
    int tok = blockIdx.x * 8 + (threadIdx.x >> 5);
    int lane = threadIdx.x & 31;
    const float* tr = g_TR + (size_t)tok*H_;
    float ax = 0.f, ay = 0.f, az = 0.f, aw = 0.f;
    #pragma unroll
    for (int i = 0; i < 8; i++) {
        int c = lane + 32*i;
        float x = tr[c];
        ax += x * g_QK[0*H_ + c];
        ay += x * g_QK[1*H_ + c];
        az += x * g_QK[2*H_ + c];
        aw += x * g_QK[3*H_ + c];
    }
    #pragma unroll
    for (int o = 16; o; o >>= 1) {
        ax += __shfl_xor_sync(0xFFFFFFFFu, ax, o);
        ay += __shfl_xor_sync(0xFFFFFFFFu, ay, o);
        az += __shfl_xor_sync(0xFFFFFFFFu, az, o);
        aw += __shfl_xor_sync(0xFFFFFFFFu, aw, o);
    }
    if (lane == 0) g_Ltok[tok] = make_float4(ax, ay, az, aw);
}

// ===== weight splits =====
__global__ void k_esplit(const float* __restrict__ src, __nv_bfloat16* __restrict__ dh,
                         __nv_bfloat16* __restrict__ dl) {
    int o = blockIdx.x * 256 + threadIdx.x;
    __nv_bfloat16 hh, ll; split_bf16(src[o], hh, ll);
    dh[o] = hh; dl[o] = ll;
}
__global__ void k_tsplit(const float* __restrict__ src, __nv_bfloat16* __restrict__ dh,
                         __nv_bfloat16* __restrict__ dl, int R, int C) {
    int o = blockIdx.x * 256 + threadIdx.x;       // o = n*R + k
    int n = o / R, k = o - n*R;
    __nv_bfloat16 hh, ll; split_bf16(src[(size_t)k*C + n], hh, ll);
    dh[o] = hh; dl[o] = ll;
}

// ================= span kernel: one warp per span ============================
__global__ __launch_bounds__(256) void k_span(const int* __restrict__ span_ids,
                                              const void* __restrict__ maskp) {
    int sp = blockIdx.x * 8 + (threadIdx.x >> 5);
    int lane = threadIdx.x & 31;
    int start = span_ids[2*sp];
    int end   = span_ids[2*sp + 1];
    int len   = read_mask(maskp, sp) ? (end - start) : 0;
    int boff  = (sp >> 13) * S_;              // batch token offset

    int w = lane & 15;
    int gt = boff + min(max(start + w, 0), S_ - 1);
    bool valid = (w < len);

    float4 L = valid ? g_Ltok[gt] : make_float4(NEGV, NEGV, NEGV, NEGV);
    float mx = L.x, my = L.y, mz = L.z, mw = L.w;
    #pragma unroll
    for (int o = 8; o; o >>= 1) {
        mx = fmaxf(mx, __shfl_xor_sync(0xFFFFFFFFu, mx, o, 16));
        my = fmaxf(my, __shfl_xor_sync(0xFFFFFFFFu, my, o, 16));
        mz = fmaxf(mz, __shfl_xor_sync(0xFFFFFFFFu, mz, o, 16));
        mw = fmaxf(mw, __shfl_xor_sync(0xFFFFFFFFu, mw, o, 16));
    }
    float ex = valid ? expf(L.x - mx) : 0.f;
    float ey = valid ? expf(L.y - my) : 0.f;
    float ez = valid ? expf(L.z - mz) : 0.f;
    float ew = valid ? expf(L.w - mw) : 0.f;
    float sx = ex, sy = ey, sz = ez, sw = ew;
    #pragma unroll
    for (int o = 8; o; o >>= 1) {
        sx += __shfl_xor_sync(0xFFFFFFFFu, sx, o, 16);
        sy += __shfl_xor_sync(0xFFFFFFFFu, sy, o, 16);
        sz += __shfl_xor_sync(0xFFFFFFFFu, sz, o, 16);
        sw += __shfl_xor_sync(0xFFFFFFFFu, sw, o, 16);
    }
    float a0 = len ? ex / sx : 0.f;
    float a1 = len ? ey / sy : 0.f;
    float a2 = len ? ez / sz : 0.f;
    float a3 = len ? ew / sw : 0.f;

    // pooling: lane owns cols [4*lane,4*lane+3] (heads 0/1) and +128 (heads 2/3)
    int hsel = lane >> 4;
    float acc0[4] = {0,0,0,0}, acc1[4] = {0,0,0,0};
    for (int ww = 0; ww < len; ww++) {
        int tw  = __shfl_sync(0xFFFFFFFFu, gt, ww);
        float b0 = __shfl_sync(0xFFFFFFFFu, a0, ww);
        float b1 = __shfl_sync(0xFFFFFFFFu, a1, ww);
        float b2 = __shfl_sync(0xFFFFFFFFu, a2, ww);
        float b3 = __shfl_sync(0xFFFFFFFFu, a3, ww);
        float s0 = hsel ? b1 : b0;
        float s1 = hsel ? b3 : b2;
        float4 v0 = *(const float4*)(g_Vtok + (size_t)tw*H_ + 4*lane);
        float4 v1 = *(const float4*)(g_Vtok + (size_t)tw*H_ + 128 + 4*lane);
        acc0[0] += s0*v0.x; acc0[1] += s0*v0.y; acc0[2] += s0*v0.z; acc0[3] += s0*v0.w;
        acc1[0] += s1*v1.x; acc1[1] += s1*v1.y; acc1[2] += s1*v1.z; acc1[3] += s1*v1.w;
    }
    union { __nv_bfloat16 b[4]; uint2 u; } H0, L0, H1, L1;
    #pragma unroll
    for (int e = 0; e < 4; e++) {
        split_bf16(acc0[e], H0.b[e], L0.b[e]);
        split_bf16(acc1[e], H1.b[e], L1.b[e]);
    }
    size_t base = (size_t)sp*H_ + 4*lane;
    *(uint2*)(g_Ctxh + base)       = H0.u;
    *(uint2*)(g_Ctxl + base)       = L0.u;
    *(uint2*)(g_Ctxh + base + 128) = H1.u;
    *(uint2*)(g_Ctxl + base + 128) = L1.u;
}

// ================= mma.sync bf16 GEMM, 3-term compensated ====================
#define PADK     40
#define MATSZ    (128*PADK)
#define STAGEB   (4*MATSZ*2)
#define NBUF     4
#define GSMEM_BYTES (NBUF*STAGEB)     // 163840

__device__ __forceinline__ void stage_load(uint32_t sbase, int buf,
        const __nv_bfloat16* __restrict__ Ah, const __nv_bfloat16* __restrict__ Al,
        const __nv_bfloat16* __restrict__ Bh, const __nv_bfloat16* __restrict__ Bl,
        int row0, int col0, int K, int kb, int tid) {
    uint32_t sb = sbase + buf*STAGEB;
    const __nv_bfloat16* P[4] = {Ah, Al, Bh, Bl};
    #pragma unroll
    for (int m = 0; m < 4; m++) {
        int r0 = (m < 2) ? row0 : col0;
        const __nv_bfloat16* p = P[m];
        #pragma unroll
        for (int half = 0; half < 2; half++) {
            int idx = tid + (half << 8);
            int row = idx >> 2, kc = idx & 3;
            cp16(sb + m*(MATSZ*2) + row*(PADK*2) + kc*16,
                 p + (size_t)(r0 + row)*K + kb + kc*8);
        }
    }
    CP_COMMIT();
}

template<int EPI>
__global__ __launch_bounds__(256)
void k_gemm(const __nv_bfloat16* __restrict__ Ah, const __nv_bfloat16* __restrict__ Al,
            const __nv_bfloat16* __restrict__ Bh, const __nv_bfloat16* __restrict__ Bl,
            const float* __restrict__ bias, float* __restrict__ C,
            __nv_bfloat16* __restrict__ Oh, __nv_bfloat16* __restrict__ Ol,
            const __nv_bfloat16* __restrict__ Rh, const __nv_bfloat16* __restrict__ Rl,
            int K, int N) {
    extern __shared__ __nv_bfloat16 smem[];
    uint32_t sbase = smem_u32(smem);
    const int tid = threadIdx.x, wid = tid >> 5, lane = tid & 31;
    const int row0 = blockIdx.y * 128, col0 = blockIdx.x * 128;
    const int wm = (wid >> 2) * 64;
    const int wn = (wid & 3) * 32;
    const int NSTG = K >> 5;

    const uint32_t aoff = ((lane & 15) * PADK + ((lane >> 4) << 3)) * 2;
    const uint32_t boff = (((((lane >> 4) << 3) + (lane & 7)) * PADK) + (((lane >> 3) & 1) << 3)) * 2;

    float acc[4][4][4];
    #pragma unroll
    for (int mi = 0; mi < 4; mi++)
        #pragma unroll
        for (int ni = 0; ni < 4; ni++)
            #pragma unroll
            for (int e = 0; e < 4; e++) acc[mi][ni][e] = 0.f;

    stage_load(sbase, 0, Ah, Al, Bh, Bl, row0, col0, K, 0,  tid);
    stage_load(sbase, 1, Ah, Al, Bh, Bl, row0, col0, K, 32, tid);
    stage_load(sbase, 2, Ah, Al, Bh, Bl, row0, col0, K, 64, tid);

    for (int s = 0; s < NSTG; s++) {
        CP_WAIT(2);
        __syncthreads();
        uint32_t sb = sbase + (s & 3)*STAGEB;
        uint32_t sAh = sb,                sAl = sb + MATSZ*2;
        uint32_t sBh = sb + 2*MATSZ*2,    sBl = sb + 3*MATSZ*2;

        #pragma unroll
        for (int kk = 0; kk < 2; kk++) {
            uint32_t kby = kk * 32;
            uint32_t a[4][4], bh[4][2], bl[4][2];
            #pragma unroll
            for (int mi = 0; mi < 4; mi++)
                ldsm4(a[mi][0], a[mi][1], a[mi][2], a[mi][3],
                      sAh + aoff + (wm + mi*16)*(PADK*2) + kby);
            #pragma unroll
            for (int nj = 0; nj < 2; nj++)
                ldsm4(bh[2*nj][0], bh[2*nj][1], bh[2*nj+1][0], bh[2*nj+1][1],
                      sBh + boff + (wn + nj*16)*(PADK*2) + kby);
            #pragma unroll
            for (int mi = 0; mi < 4; mi++)
                #pragma unroll
                for (int ni = 0; ni < 4; ni++)
                    mma16816(acc[mi][ni], a[mi][0], a[mi][1], a[mi][2], a[mi][3],
                             bh[ni][0], bh[ni][1]);
            #pragma unroll
            for (int nj = 0; nj < 2; nj++)
                ldsm4(bl[2*nj][0], bl[2*nj][1], bl[2*nj+1][0], bl[2*nj+1][1],
                      sBl + boff + (wn + nj*16)*(PADK*2) + kby);
            #pragma unroll
            for (int mi = 0; mi < 4; mi++)
                #pragma unroll
                for (int ni = 0; ni < 4; ni++)
                    mma16816(acc[mi][ni], a[mi][0], a[mi][1], a[mi][2], a[mi][3],
                             bl[ni][0], bl[ni][1]);
            #pragma unroll
            for (int mi = 0; mi < 4; mi++)
                ldsm4(a[mi][0], a[mi][1], a[mi][2], a[mi][3],
                      sAl + aoff + (wm + mi*16)*(PADK*2) + kby);
            #pragma unroll
            for (int mi = 0; mi < 4; mi++)
                #pragma unroll
                for (int ni = 0; ni < 4; ni++)
                    mma16816(acc[mi][ni], a[mi][0], a[mi][1], a[mi][2], a[mi][3],
                             bh[ni][0], bh[ni][1]);
        }
        int nx = s + 3;
        if (nx < NSTG) stage_load(sbase, nx & 3, Ah, Al, Bh, Bl, row0, col0, K, nx << 5, tid);
        else           CP_COMMIT();
    }

    // ---- epilogue ----
    #pragma unroll
    for (int mi = 0; mi < 4; mi++) {
        #pragma unroll
        for (int ni = 0; ni < 4; ni++) {
            int gr0 = row0 + wm + mi*16 + (lane >> 2);
            int gc  = col0 + wn + ni*8 + ((lane & 3) << 1);
            float b0 = bias[gc], b1 = bias[gc + 1];
            float v00 = acc[mi][ni][0] + b0, v01 = acc[mi][ni][1] + b1;
            float v10 = acc[mi][ni][2] + b0, v11 = acc[mi][ni][3] + b1;
            if (EPI == 0) {
                *(float2*)(C + (size_t)gr0*N + gc)       = make_float2(v00, v01);
                *(float2*)(C + (size_t)(gr0+8)*N + gc)   = make_float2(v10, v11);
            } else if (EPI == 1) {
                union { __nv_bfloat16 b[2]; uint32_t u; } h0, l0, h1, l1;
                float w00 = fmaxf(v00, 0.f), w01 = fmaxf(v01, 0.f);
                float w10 = fmaxf(v10, 0.f), w11 = fmaxf(v11, 0.f);
                split_bf16(w00, h0.b[0], l0.b[0]); split_bf16(w01, h0.b[1], l0.b[1]);
                split_bf16(w10, h1.b[0], l1.b[0]); split_bf16(w11, h1.b[1], l1.b[1]);
                *(uint32_t*)(Oh + (size_t)gr0*N + gc)     = h0.u;
                *(uint32_t*)(Ol + (size_t)gr0*N + gc)     = l0.u;
                *(uint32_t*)(Oh + (size_t)(gr0+8)*N + gc) = h1.u;
                *(uint32_t*)(Ol + (size_t)(gr0+8)*N + gc) = l1.u;
            } else {
                union { __nv_bfloat16 b[2]; uint32_t u; } rh0, rl0, rh1, rl1;
                rh0.u = *(const uint32_t*)(Rh + (size_t)gr0*N + gc);
                rl0.u = *(const uint32_t*)(Rl + (size_t)gr0*N + gc);
                rh1.u = *(const uint32_t*)(Rh + (size_t)(gr0+8)*N + gc);
                rl1.u = *(const uint32_t*)(Rl + (size_t)(gr0+8)*N + gc);
                v00 += __bfloat162float(rh0.b[0]) + __bfloat162float(rl0.b[0]);
                v01 += __bfloat162float(rh0.b[1]) + __bfloat162float(rl0.b[1]);
                v10 += __bfloat162float(rh1.b[0]) + __bfloat162float(rl1.b[0]);
                v11 += __bfloat162float(rh1.b[1]) + __bfloat162float(rl1.b[1]);
                *(float2*)(C + (size_t)gr0*N + gc)       = make_float2(v00, v01);
                *(float2*)(C + (size_t)(gr0+8)*N + gc)   = make_float2(v10, v11);
            }
        }
    }
}

// ================= LayerNorm variants =================
__global__ __launch_bounds__(256) void k_ln_bf16(const float* __restrict__ X,
        __nv_bfloat16* __restrict__ Yh, __nv_bfloat16* __restrict__ Yl,
        const float* __restrict__ g, const float* __restrict__ bb) {
    int gw = (blockIdx.x * 256 + threadIdx.x) >> 5;
    int lane = threadIdx.x & 31;
    const float* x = X + (size_t)gw * H_;
    float v[8]; float s = 0.f;
    #pragma unroll
    for (int i = 0; i < 8; i++) { v[i] = x[lane + 32*i]; s += v[i]; }
    #pragma unroll
    for (int o = 16; o; o >>= 1) s += __shfl_xor_sync(0xFFFFFFFFu, s, o);
    float mean = s * (1.f/H_);
    float sv = 0.f;
    #pragma unroll
    for (int i = 0; i < 8; i++) { float d = v[i] - mean; sv += d*d; }
    #pragma unroll
    for (int o = 16; o; o >>= 1) sv += __shfl_xor_sync(0xFFFFFFFFu, sv, o);
    float inv = rsqrtf(sv * (1.f/H_) + 1e-5f);
    #pragma unroll
    for (int i = 0; i < 8; i++) {
        int c = lane + 32*i;
        float yv = (v[i] - mean) * inv * g[c] + bb[c];
        __nv_bfloat16 hh, ll; split_bf16(yv, hh, ll);
        Yh[(size_t)gw*H_ + c] = hh;
        Yl[(size_t)gw*H_ + c] = ll;
    }
}

__global__ __launch_bounds__(256) void k_ln_final(const float* __restrict__ X, float* __restrict__ Yo,
        const float* __restrict__ g, const float* __restrict__ bb, const void* __restrict__ maskp) {
    int gw = (blockIdx.x * 256 + threadIdx.x) >> 5;
    int lane = threadIdx.x & 31;
    const float* x = X + (size_t)gw * H_;
    float v[8]; float s = 0.f;
    #pragma unroll
    for (int i = 0; i < 8; i++) { v[i] = x[lane + 32*i]; s += v[i]; }
    #pragma unroll
    for (int o = 16; o; o >>= 1) s += __shfl_xor_sync(0xFFFFFFFFu, s, o);
    float mean = s * (1.f/H_);
    float sv = 0.f;
    #pragma unroll
    for (int i = 0; i < 8; i++) { float d = v[i] - mean; sv += d*d; }
    #pragma unroll
    for (int o = 16; o; o >>= 1) sv += __shfl_xor_sync(0xFFFFFFFFu, sv, o);
    float inv = rsqrtf(sv * (1.f/H_) + 1e-5f);
    float mf = read_mask(maskp, gw) ? 1.f : 0.f;
    float* y = Yo + (size_t)gw * H_;
    #pragma unroll
    for (int i = 0; i < 8; i++) {
        int c = lane + 32*i;
        y[c] = ((v[i] - mean) * inv * g[c] + bb[c]) * mf;
    }
}

// ================= launch =================
extern "C" void kernel_launch(void* const* d_in, const int* in_sizes, int n_in,
                              void* d_out, int out_size) {
    const float* tok   = (const float*)d_in[0];
    const int*   sids  = (const int*)  d_in[1];
    const void*  masks =               d_in[2];
    const float* dq    = (const float*)d_in[4];
    const float* wq    = (const float*)d_in[5];
    const float* wk    = (const float*)d_in[6];
    const float* wv    = (const float*)d_in[7];
    const float* bqkv  = (const float*)d_in[8];
    const float* wo    = (const float*)d_in[9];
    const float* bo    = (const float*)d_in[10];
    const float* lng   = (const float*)d_in[11];
    const float* lnb   = (const float*)d_in[12];
    const float* w1    = (const float*)d_in[13];
    const float* b1    = (const float*)d_in[14];
    const float* w2    = (const float*)d_in[15];
    const float* b2    = (const float*)d_in[16];
    float* out = (float*)d_out;

    float *T1, *BO;
    __nv_bfloat16 *Ch, *Cl, *Yh, *Yl, *Fh, *Fl, *WOh, *WOl, *W1Th, *W1Tl, *W2Th, *W2Tl;
    cudaGetSymbolAddress((void**)&T1,  g_T1);
    cudaGetSymbolAddress((void**)&BO,  g_BO);
    cudaGetSymbolAddress((void**)&Ch,  g_Ctxh);
    cudaGetSymbolAddress((void**)&Cl,  g_Ctxl);
    cudaGetSymbolAddress((void**)&Yh,  g_Yh);
    cudaGetSymbolAddress((void**)&Yl,  g_Yl);
    cudaGetSymbolAddress((void**)&Fh,  g_Fh);
    cudaGetSymbolAddress((void**)&Fl,  g_Fl);
    cudaGetSymbolAddress((void**)&WOh, g_WOh);
    cudaGetSymbolAddress((void**)&WOl, g_WOl);
    cudaGetSymbolAddress((void**)&W1Th, g_W1Th);
    cudaGetSymbolAddress((void**)&W1Tl, g_W1Tl);
    cudaGetSymbolAddress((void**)&W2Th, g_W2Th);
    cudaGetSymbolAddress((void**)&W2Tl, g_W2Tl);

    cudaFuncSetAttribute(k_gemm<0>, cudaFuncAttributeMaxDynamicSharedMemorySize, GSMEM_BYTES);
    cudaFuncSetAttribute(k_gemm<1>, cudaFuncAttributeMaxDynamicSharedMemorySize, GSMEM_BYTES);
    cudaFuncSetAttribute(k_gemm<2>, cudaFuncAttributeMaxDynamicSharedMemorySize, GSMEM_BYTES);

    k_detect_mask<<<1, 256>>>((const unsigned int*)masks);
    k_addpe<<<(B_*S_*H_)/256, 256>>>(tok);
    k_precompute<<<1, 256>>>(dq, wq, wk, bqkv, wo, bo);
    k_vtok<<<(B_*S_)/8, 256>>>(wv);
    k_ltok<<<(B_*S_)/8, 256>>>();
    k_esplit<<<(H_*H_)/256, 256>>>(wo, WOh, WOl);
    k_tsplit<<<(FF_*H_)/256, 256>>>(w1, W1Th, W1Tl, H_, FF_);
    k_tsplit<<<(FF_*H_)/256, 256>>>(w2, W2Th, W2Tl, FF_, H_);
    k_span<<<NSPAN/8, 256>>>(sids, masks);

    // GEMM1': T1 = Ctx(32768x256) @ WO^T (N=256) + BO
    k_gemm<0><<<dim3(2, NSPAN/128), 256, GSMEM_BYTES>>>(Ch, Cl, WOh, WOl, BO, T1,
                                                        nullptr, nullptr, nullptr, nullptr, H_, H_);
    // Y = LN(T1) -> bf16 hi/lo
    k_ln_bf16<<<NSPAN/8, 256>>>(T1, Yh, Yl, lng, lnb);
    // GEMM2: F = relu(Y @ W1T^T (N=1024) + b1) -> bf16 hi/lo
    k_gemm<1><<<dim3(8, NSPAN/128), 256, GSMEM_BYTES>>>(Yh, Yl, W1Th, W1Tl, b1, nullptr,
                                                        Fh, Fl, nullptr, nullptr, H_, FF_);
    // GEMM3: T1 = F @ W2T^T (N=256) + b2 + Y
    k_gemm<2><<<dim3(2, NSPAN/128), 256, GSMEM_BYTES>>>(Fh, Fl, W2Th, W2Tl, b2, T1,
                                                        nullptr, nullptr, Yh, Yl, FF_, H_);
    // out = LN(T1) * mask
    k_ln_final<<<NSPAN/8, 256>>>(T1, out, lng, lnb, masks);
}

// round 8
// speedup vs baseline: 3.0242x; 1.0620x over previous
#include <cuda_runtime.h>
#include <cuda_bf16.h>
#include <cstdint>
#include <math.h>

// ================= problem constants =================
#define B_    4
#define S_    512
#define NS_   8192
#define MAXW  16
#define H_    256
#define NH_   4
#define DH_   64
#define FF_   1024
#define NSPAN (B_*NS_)          // 32768
#define NEGV  (-1000000000.0f)

// ================= device scratch =================
__device__ float g_TR[B_*S_*H_];
__device__ float g_QK[NH_*H_];
__device__ float g_BO[H_];
__device__ float g_Vtok[B_*S_*H_];               // TR @ w_v^T  (2 MB)
__device__ float4 g_Ltok[B_*S_];                 // per-token logits (4 heads)
__device__ float g_T1[(size_t)NSPAN*H_];
__device__ __nv_bfloat16 g_Ctxh[(size_t)NSPAN*H_];
__device__ __nv_bfloat16 g_Ctxl[(size_t)NSPAN*H_];
__device__ __nv_bfloat16 g_Yh[(size_t)NSPAN*H_];
__device__ __nv_bfloat16 g_Yl[(size_t)NSPAN*H_];
__device__ __nv_bfloat16 g_Fh[(size_t)NSPAN*FF_];
__device__ __nv_bfloat16 g_Fl[(size_t)NSPAN*FF_];
__device__ __nv_bfloat16 g_WOh[H_*H_];           // w_o split, [n][k]
__device__ __nv_bfloat16 g_WOl[H_*H_];
__device__ __nv_bfloat16 g_W1Th[FF_*H_];         // w1^T split  [1024][256]
__device__ __nv_bfloat16 g_W1Tl[FF_*H_];
__device__ __nv_bfloat16 g_W2Th[H_*FF_];         // w2^T split  [256][1024]
__device__ __nv_bfloat16 g_W2Tl[H_*FF_];
__device__ int g_mask_is_byte;

__device__ __forceinline__ void split_bf16(float x, __nv_bfloat16& h, __nv_bfloat16& l) {
    h = __float2bfloat16(x);
    l = __float2bfloat16(x - __bfloat162float(h));
}

// ================= small PTX helpers =================
__device__ __forceinline__ uint32_t smem_u32(const void* p) {
    uint32_t a;
    asm("{ .reg .u64 t; cvta.to.shared.u64 t, %1; cvt.u32.u64 %0, t; }" : "=r"(a) : "l"(p));
    return a;
}
__device__ __forceinline__ void cp16(uint32_t s, const void* g) {
    asm volatile("cp.async.cg.shared.global [%0], [%1], 16;" :: "r"(s), "l"(g));
}
#define CP_COMMIT() asm volatile("cp.async.commit_group;" ::: "memory")
#define CP_WAIT(n)  asm volatile("cp.async.wait_group %0;" :: "n"(n) : "memory")

__device__ __forceinline__ void ldsm4(uint32_t& r0, uint32_t& r1, uint32_t& r2, uint32_t& r3, uint32_t a) {
    asm volatile("ldmatrix.sync.aligned.m8n8.x4.shared.b16 {%0,%1,%2,%3}, [%4];"
                 : "=r"(r0), "=r"(r1), "=r"(r2), "=r"(r3) : "r"(a));
}
__device__ __forceinline__ void mma16816(float* d, uint32_t a0, uint32_t a1, uint32_t a2, uint32_t a3,
                                         uint32_t b0, uint32_t b1) {
    asm volatile("mma.sync.aligned.m16n8k16.row.col.f32.bf16.bf16.f32 "
                 "{%0,%1,%2,%3}, {%4,%5,%6,%7}, {%8,%9}, {%0,%1,%2,%3};"
                 : "+f"(d[0]), "+f"(d[1]), "+f"(d[2]), "+f"(d[3])
                 : "r"(a0), "r"(a1), "r"(a2), "r"(a3), "r"(b0), "r"(b1));
}

// ================= mask format detection =================
__global__ void k_detect_mask(const unsigned int* __restrict__ m) {
    __shared__ int found;
    if (threadIdx.x == 0) found = 0;
    __syncthreads();
    unsigned v = m[threadIdx.x];
    if (v > 1u) atomicOr(&found, 1);
    __syncthreads();
    if (threadIdx.x == 0) g_mask_is_byte = found;
}
__device__ __forceinline__ int read_mask(const void* p, int i) {
    if (g_mask_is_byte) return ((const unsigned char*)p)[i] != 0;
    return ((const int*)p)[i] != 0;
}

// ================= token_reps + positional encoding =================
__global__ void k_addpe(const float* __restrict__ tok) {
    int idx = blockIdx.x * 256 + threadIdx.x;
    int c = idx & 255;
    int s = (idx >> 8) & (S_ - 1);
    double div = exp((double)(c & ~1) * (-9.210340371976184 / 256.0));
    double arg = (double)s * div;
    float pe = (c & 1) ? (float)cos(arg) : (float)sin(arg);
    g_TR[idx] = tok[idx] + pe;
}

// ================= precompute: qk (scaled), output bias =================
__global__ void k_precompute(const float* __restrict__ dq, const float* __restrict__ wq,
                             const float* __restrict__ wk, const float* __restrict__ bqkv,
                             const float* __restrict__ wo, const float* __restrict__ bo) {
    __shared__ float qs[H_];
    int t = threadIdx.x;
    float s = bqkv[t];
    for (int c = 0; c < H_; c++) s += dq[c] * wq[t*H_ + c];
    qs[t] = s;
    __syncthreads();
    #pragma unroll
    for (int h = 0; h < NH_; h++) {
        float acc = 0.f;
        for (int d = 0; d < DH_; d++) acc += qs[h*DH_ + d] * wk[(h*DH_ + d)*H_ + t];
        g_QK[h*H_ + t] = 0.125f * acc;
    }
    float bacc = bo[t] + dq[t];
    for (int i = 0; i < H_; i++) bacc += bqkv[2*H_ + i] * wo[t*H_ + i];
    g_BO[t] = bacc;
}

// ================= fused prep: vtok | ltok | weight splits ==================
// blocks [0,256):    V_tok (8 tokens/block, float4 weights, unrolled)
// blocks [256,512):  L_tok (8 tokens/block, warp each)
// blocks [512,768):  esplit wo
// blocks [768,1792): tsplit w1 ([256][1024] -> [1024][256])
// blocks [1792,2816): tsplit w2 ([1024][256] -> [256][1024])
__global__ __launch_bounds__(256) void k_prep(const float* __restrict__ wv,
                                              const float* __restrict__ wo,
                                              const float* __restrict__ w1,
                                              const float* __restrict__ w2) {
    int bid = blockIdx.x;
    int tid = threadIdx.x;
    if (bid < 256) {
        // ---- vtok ----
        __shared__ float xs[8][H_];
        int t0 = bid * 8;
        #pragma unroll
        for (int r = 0; r < 8; r++) xs[r][tid] = g_TR[(t0 + r)*H_ + tid];
        __syncthreads();
        float acc[8] = {0,0,0,0,0,0,0,0};
        const float4* wr = (const float4*)(wv + (size_t)tid*H_);
        #pragma unroll 8
        for (int k4 = 0; k4 < H_/4; k4++) {
            float4 w = wr[k4];
            int k = k4 << 2;
            #pragma unroll
            for (int r = 0; r < 8; r++)
                acc[r] += xs[r][k]*w.x + xs[r][k+1]*w.y + xs[r][k+2]*w.z + xs[r][k+3]*w.w;
        }
        #pragma unroll
        for (int r = 0; r < 8; r++) g_Vtok[(t0 + r)*H_ + tid] = acc[r];
    } else if (bid < 512) {
        // ---- ltok ----
        int tok = (bid - 256) * 8 + (tid >> 5);
        int lane = tid & 31;
        const float* tr = g_TR + (size_t)tok*H_;
        float ax = 0.f, ay = 0.f, az = 0.f, aw = 0.f;
        #pragma unroll
        for (int i = 0; i < 8; i++) {
            int c = lane + 32*i;
            float x = tr[c];
            ax += x * g_QK[0*H_ + c];
            ay += x * g_QK[1*H_ + c];
            az += x * g_QK[2*H_ + c];
            aw += x * g_QK[3*H_ + c];
        }
        #pragma unroll
        for (int o = 16; o; o >>= 1) {
            ax += __shfl_xor_sync(0xFFFFFFFFu, ax, o);
            ay += __shfl_xor_sync(0xFFFFFFFFu, ay, o);
            az += __shfl_xor_sync(0xFFFFFFFFu, az, o);
            aw += __shfl_xor_sync(0xFFFFFFFFu, aw, o);
        }
        if (lane == 0) g_Ltok[tok] = make_float4(ax, ay, az, aw);
    } else if (bid < 768) {
        // ---- esplit wo ----
        int o = (bid - 512) * 256 + tid;
        __nv_bfloat16 hh, ll; split_bf16(wo[o], hh, ll);
        g_WOh[o] = hh; g_WOl[o] = ll;
    } else if (bid < 1792) {
        // ---- tsplit w1: o = n*256 + k, reads w1[k*1024 + n] ----
        int o = (bid - 768) * 256 + tid;
        int n = o >> 8, k = o & 255;
        __nv_bfloat16 hh, ll; split_bf16(w1[(size_t)k*FF_ + n], hh, ll);
        g_W1Th[o] = hh; g_W1Tl[o] = ll;
    } else {
        // ---- tsplit w2: o = n*1024 + k, reads w2[k*256 + n] ----
        int o = (bid - 1792) * 256 + tid;
        int n = o >> 10, k = o & 1023;
        __nv_bfloat16 hh, ll; split_bf16(w2[(size_t)k*H_ + n], hh, ll);
        g_W2Th[o] = hh; g_W2Tl[o] = ll;
    }
}

// ================= span kernel: one warp per span ============================
__global__ __launch_bounds__(256) void k_span(const int* __restrict__ span_ids,
                                              const void* __restrict__ maskp) {
    int sp = blockIdx.x * 8 + (threadIdx.x >> 5);
    int lane = threadIdx.x & 31;
    int start = span_ids[2*sp];
    int end   = span_ids[2*sp + 1];
    int len   = read_mask(maskp, sp) ? (end - start) : 0;
    int boff  = (sp >> 13) * S_;              // batch token offset

    int w = lane & 15;
    int gt = boff + min(max(start + w, 0), S_ - 1);
    bool valid = (w < len);

    float4 L = valid ? g_Ltok[gt] : make_float4(NEGV, NEGV, NEGV, NEGV);
    float mx = L.x, my = L.y, mz = L.z, mw = L.w;
    #pragma unroll
    for (int o = 8; o; o >>= 1) {
        mx = fmaxf(mx, __shfl_xor_sync(0xFFFFFFFFu, mx, o, 16));
        my = fmaxf(my, __shfl_xor_sync(0xFFFFFFFFu, my, o, 16));
        mz = fmaxf(mz, __shfl_xor_sync(0xFFFFFFFFu, mz, o, 16));
        mw = fmaxf(mw, __shfl_xor_sync(0xFFFFFFFFu, mw, o, 16));
    }
    float ex = valid ? expf(L.x - mx) : 0.f;
    float ey = valid ? expf(L.y - my) : 0.f;
    float ez = valid ? expf(L.z - mz) : 0.f;
    float ew = valid ? expf(L.w - mw) : 0.f;
    float sx = ex, sy = ey, sz = ez, sw = ew;
    #pragma unroll
    for (int o = 8; o; o >>= 1) {
        sx += __shfl_xor_sync(0xFFFFFFFFu, sx, o, 16);
        sy += __shfl_xor_sync(0xFFFFFFFFu, sy, o, 16);
        sz += __shfl_xor_sync(0xFFFFFFFFu, sz, o, 16);
        sw += __shfl_xor_sync(0xFFFFFFFFu, sw, o, 16);
    }
    // invalid lanes (w >= len) have e* = 0 -> attn weight 0; len==0 handled below
    float a0 = len ? ex / sx : 0.f;
    float a1 = len ? ey / sy : 0.f;
    float a2 = len ? ez / sz : 0.f;
    float a3 = len ? ew / sw : 0.f;

    // pooling, fully unrolled: weights are 0 beyond len, addresses are clamped-valid
    int hsel = lane >> 4;
    float acc0[4] = {0,0,0,0}, acc1[4] = {0,0,0,0};
    #pragma unroll
    for (int ww = 0; ww < MAXW; ww++) {
        int tw  = __shfl_sync(0xFFFFFFFFu, gt, ww);
        float b0 = __shfl_sync(0xFFFFFFFFu, a0, ww);
        float b1 = __shfl_sync(0xFFFFFFFFu, a1, ww);
        float b2 = __shfl_sync(0xFFFFFFFFu, a2, ww);
        float b3 = __shfl_sync(0xFFFFFFFFu, a3, ww);
        float s0 = hsel ? b1 : b0;
        float s1 = hsel ? b3 : b2;
        float4 v0 = *(const float4*)(g_Vtok + (size_t)tw*H_ + 4*lane);
        float4 v1 = *(const float4*)(g_Vtok + (size_t)tw*H_ + 128 + 4*lane);
        acc0[0] += s0*v0.x; acc0[1] += s0*v0.y; acc0[2] += s0*v0.z; acc0[3] += s0*v0.w;
        acc1[0] += s1*v1.x; acc1[1] += s1*v1.y; acc1[2] += s1*v1.z; acc1[3] += s1*v1.w;
    }
    union { __nv_bfloat16 b[4]; uint2 u; } H0, L0, H1, L1;
    #pragma unroll
    for (int e = 0; e < 4; e++) {
        split_bf16(acc0[e], H0.b[e], L0.b[e]);
        split_bf16(acc1[e], H1.b[e], L1.b[e]);
    }
    size_t base = (size_t)sp*H_ + 4*lane;
    *(uint2*)(g_Ctxh + base)       = H0.u;
    *(uint2*)(g_Ctxl + base)       = L0.u;
    *(uint2*)(g_Ctxh + base + 128) = H1.u;
    *(uint2*)(g_Ctxl + base + 128) = L1.u;
}

// ================= mma.sync bf16 GEMM, 3-term compensated ====================
#define PADK     40
#define MATSZ    (128*PADK)
#define STAGEB   (4*MATSZ*2)
#define NBUF     4
#define GSMEM_BYTES (NBUF*STAGEB)     // 163840

__device__ __forceinline__ void stage_load(uint32_t sbase, int buf,
        const __nv_bfloat16* __restrict__ Ah, const __nv_bfloat16* __restrict__ Al,
        const __nv_bfloat16* __restrict__ Bh, const __nv_bfloat16* __restrict__ Bl,
        int row0, int col0, int K, int kb, int tid) {
    uint32_t sb = sbase + buf*STAGEB;
    const __nv_bfloat16* P[4] = {Ah, Al, Bh, Bl};
    #pragma unroll
    for (int m = 0; m < 4; m++) {
        int r0 = (m < 2) ? row0 : col0;
        const __nv_bfloat16* p = P[m];
        #pragma unroll
        for (int half = 0; half < 2; half++) {
            int idx = tid + (half << 8);
            int row = idx >> 2, kc = idx & 3;
            cp16(sb + m*(MATSZ*2) + row*(PADK*2) + kc*16,
                 p + (size_t)(r0 + row)*K + kb + kc*8);
        }
    }
    CP_COMMIT();
}

template<int EPI>
__global__ __launch_bounds__(256)
void k_gemm(const __nv_bfloat16* __restrict__ Ah, const __nv_bfloat16* __restrict__ Al,
            const __nv_bfloat16* __restrict__ Bh, const __nv_bfloat16* __restrict__ Bl,
            const float* __restrict__ bias, float* __restrict__ C,
            __nv_bfloat16* __restrict__ Oh, __nv_bfloat16* __restrict__ Ol,
            const __nv_bfloat16* __restrict__ Rh, const __nv_bfloat16* __restrict__ Rl,
            int K, int N) {
    extern __shared__ __nv_bfloat16 smem[];
    uint32_t sbase = smem_u32(smem);
    const int tid = threadIdx.x, wid = tid >> 5, lane = tid & 31;
    const int row0 = blockIdx.y * 128, col0 = blockIdx.x * 128;
    const int wm = (wid >> 2) * 64;
    const int wn = (wid & 3) * 32;
    const int NSTG = K >> 5;

    const uint32_t aoff = ((lane & 15) * PADK + ((lane >> 4) << 3)) * 2;
    const uint32_t boff = (((((lane >> 4) << 3) + (lane & 7)) * PADK) + (((lane >> 3) & 1) << 3)) * 2;

    float acc[4][4][4];
    #pragma unroll
    for (int mi = 0; mi < 4; mi++)
        #pragma unroll
        for (int ni = 0; ni < 4; ni++)
            #pragma unroll
            for (int e = 0; e < 4; e++) acc[mi][ni][e] = 0.f;

    stage_load(sbase, 0, Ah, Al, Bh, Bl, row0, col0, K, 0,  tid);
    stage_load(sbase, 1, Ah, Al, Bh, Bl, row0, col0, K, 32, tid);
    stage_load(sbase, 2, Ah, Al, Bh, Bl, row0, col0, K, 64, tid);

    for (int s = 0; s < NSTG; s++) {
        CP_WAIT(2);
        __syncthreads();
        uint32_t sb = sbase + (s & 3)*STAGEB;
        uint32_t sAh = sb,                sAl = sb + MATSZ*2;
        uint32_t sBh = sb + 2*MATSZ*2,    sBl = sb + 3*MATSZ*2;

        #pragma unroll
        for (int kk = 0; kk < 2; kk++) {
            uint32_t kby = kk * 32;
            uint32_t a[4][4], bh[4][2], bl[4][2];
            #pragma unroll
            for (int mi = 0; mi < 4; mi++)
                ldsm4(a[mi][0], a[mi][1], a[mi][2], a[mi][3],
                      sAh + aoff + (wm + mi*16)*(PADK*2) + kby);
            #pragma unroll
            for (int nj = 0; nj < 2; nj++)
                ldsm4(bh[2*nj][0], bh[2*nj][1], bh[2*nj+1][0], bh[2*nj+1][1],
                      sBh + boff + (wn + nj*16)*(PADK*2) + kby);
            #pragma unroll
            for (int mi = 0; mi < 4; mi++)
                #pragma unroll
                for (int ni = 0; ni < 4; ni++)
                    mma16816(acc[mi][ni], a[mi][0], a[mi][1], a[mi][2], a[mi][3],
                             bh[ni][0], bh[ni][1]);
            #pragma unroll
            for (int nj = 0; nj < 2; nj++)
                ldsm4(bl[2*nj][0], bl[2*nj][1], bl[2*nj+1][0], bl[2*nj+1][1],
                      sBl + boff + (wn + nj*16)*(PADK*2) + kby);
            #pragma unroll
            for (int mi = 0; mi < 4; mi++)
                #pragma unroll
                for (int ni = 0; ni < 4; ni++)
                    mma16816(acc[mi][ni], a[mi][0], a[mi][1], a[mi][2], a[mi][3],
                             bl[ni][0], bl[ni][1]);
            #pragma unroll
            for (int mi = 0; mi < 4; mi++)
                ldsm4(a[mi][0], a[mi][1], a[mi][2], a[mi][3],
                      sAl + aoff + (wm + mi*16)*(PADK*2) + kby);
            #pragma unroll
            for (int mi = 0; mi < 4; mi++)
                #pragma unroll
                for (int ni = 0; ni < 4; ni++)
                    mma16816(acc[mi][ni], a[mi][0], a[mi][1], a[mi][2], a[mi][3],
                             bh[ni][0], bh[ni][1]);
        }
        int nx = s + 3;
        if (nx < NSTG) stage_load(sbase, nx & 3, Ah, Al, Bh, Bl, row0, col0, K, nx << 5, tid);
        else           CP_COMMIT();
    }

    // ---- epilogue ----
    #pragma unroll
    for (int mi = 0; mi < 4; mi++) {
        #pragma unroll
        for (int ni = 0; ni < 4; ni++) {
            int gr0 = row0 + wm + mi*16 + (lane >> 2);
            int gc  = col0 + wn + ni*8 + ((lane & 3) << 1);
            float b0 = bias[gc], b1 = bias[gc + 1];
            float v00 = acc[mi][ni][0] + b0, v01 = acc[mi][ni][1] + b1;
            float v10 = acc[mi][ni][2] + b0, v11 = acc[mi][ni][3] + b1;
            if (EPI == 0) {
                *(float2*)(C + (size_t)gr0*N + gc)       = make_float2(v00, v01);
                *(float2*)(C + (size_t)(gr0+8)*N + gc)   = make_float2(v10, v11);
            } else if (EPI == 1) {
                union { __nv_bfloat16 b[2]; uint32_t u; } h0, l0, h1, l1;
                float w00 = fmaxf(v00, 0.f), w01 = fmaxf(v01, 0.f);
                float w10 = fmaxf(v10, 0.f), w11 = fmaxf(v11, 0.f);
                split_bf16(w00, h0.b[0], l0.b[0]); split_bf16(w01, h0.b[1], l0.b[1]);
                split_bf16(w10, h1.b[0], l1.b[0]); split_bf16(w11, h1.b[1], l1.b[1]);
                *(uint32_t*)(Oh + (size_t)gr0*N + gc)     = h0.u;
                *(uint32_t*)(Ol + (size_t)gr0*N + gc)     = l0.u;
                *(uint32_t*)(Oh + (size_t)(gr0+8)*N + gc) = h1.u;
                *(uint32_t*)(Ol + (size_t)(gr0+8)*N + gc) = l1.u;
            } else {
                union { __nv_bfloat16 b[2]; uint32_t u; } rh0, rl0, rh1, rl1;
                rh0.u = *(const uint32_t*)(Rh + (size_t)gr0*N + gc);
                rl0.u = *(const uint32_t*)(Rl + (size_t)gr0*N + gc);
                rh1.u = *(const uint32_t*)(Rh + (size_t)(gr0+8)*N + gc);
                rl1.u = *(const uint32_t*)(Rl + (size_t)(gr0+8)*N + gc);
                v00 += __bfloat162float(rh0.b[0]) + __bfloat162float(rl0.b[0]);
                v01 += __bfloat162float(rh0.b[1]) + __bfloat162float(rl0.b[1]);
                v10 += __bfloat162float(rh1.b[0]) + __bfloat162float(rl1.b[0]);
                v11 += __bfloat162float(rh1.b[1]) + __bfloat162float(rl1.b[1]);
                *(float2*)(C + (size_t)gr0*N + gc)       = make_float2(v00, v01);
                *(float2*)(C + (size_t)(gr0+8)*N + gc)   = make_float2(v10, v11);
            }
        }
    }
}

// ================= LayerNorm variants =================
__global__ __launch_bounds__(256) void k_ln_bf16(const float* __restrict__ X,
        __nv_bfloat16* __restrict__ Yh, __nv_bfloat16* __restrict__ Yl,
        const float* __restrict__ g, const float* __restrict__ bb) {
    int gw = (blockIdx.x * 256 + threadIdx.x) >> 5;
    int lane = threadIdx.x & 31;
    const float* x = X + (size_t)gw * H_;
    float v[8]; float s = 0.f;
    #pragma unroll
    for (int i = 0; i < 8; i++) { v[i] = x[lane + 32*i]; s += v[i]; }
    #pragma unroll
    for (int o = 16; o; o >>= 1) s += __shfl_xor_sync(0xFFFFFFFFu, s, o);
    float mean = s * (1.f/H_);
    float sv = 0.f;
    #pragma unroll
    for (int i = 0; i < 8; i++) { float d = v[i] - mean; sv += d*d; }
    #pragma unroll
    for (int o = 16; o; o >>= 1) sv += __shfl_xor_sync(0xFFFFFFFFu, sv, o);
    float inv = rsqrtf(sv * (1.f/H_) + 1e-5f);
    #pragma unroll
    for (int i = 0; i < 8; i++) {
        int c = lane + 32*i;
        float yv = (v[i] - mean) * inv * g[c] + bb[c];
        __nv_bfloat16 hh, ll; split_bf16(yv, hh, ll);
        Yh[(size_t)gw*H_ + c] = hh;
        Yl[(size_t)gw*H_ + c] = ll;
    }
}

__global__ __launch_bounds__(256) void k_ln_final(const float* __restrict__ X, float* __restrict__ Yo,
        const float* __restrict__ g, const float* __restrict__ bb, const void* __restrict__ maskp) {
    int gw = (blockIdx.x * 256 + threadIdx.x) >> 5;
    int lane = threadIdx.x & 31;
    const float* x = X + (size_t)gw * H_;
    float v[8]; float s = 0.f;
    #pragma unroll
    for (int i = 0; i < 8; i++) { v[i] = x[lane + 32*i]; s += v[i]; }
    #pragma unroll
    for (int o = 16; o; o >>= 1) s += __shfl_xor_sync(0xFFFFFFFFu, s, o);
    float mean = s * (1.f/H_);
    float sv = 0.f;
    #pragma unroll
    for (int i = 0; i < 8; i++) { float d = v[i] - mean; sv += d*d; }
    #pragma unroll
    for (int o = 16; o; o >>= 1) sv += __shfl_xor_sync(0xFFFFFFFFu, sv, o);
    float inv = rsqrtf(sv * (1.f/H_) + 1e-5f);
    float mf = read_mask(maskp, gw) ? 1.f : 0.f;
    float* y = Yo + (size_t)gw * H_;
    #pragma unroll
    for (int i = 0; i < 8; i++) {
        int c = lane + 32*i;
        y[c] = ((v[i] - mean) * inv * g[c] + bb[c]) * mf;
    }
}

// ================= launch =================
extern "C" void kernel_launch(void* const* d_in, const int* in_sizes, int n_in,
                              void* d_out, int out_size) {
    const float* tok   = (const float*)d_in[0];
    const int*   sids  = (const int*)  d_in[1];
    const void*  masks =               d_in[2];
    const float* dq    = (const float*)d_in[4];
    const float* wq    = (const float*)d_in[5];
    const float* wk    = (const float*)d_in[6];
    const float* wv    = (const float*)d_in[7];
    const float* bqkv  = (const float*)d_in[8];
    const float* wo    = (const float*)d_in[9];
    const float* bo    = (const float*)d_in[10];
    const float* lng   = (const float*)d_in[11];
    const float* lnb   = (const float*)d_in[12];
    const float* w1    = (const float*)d_in[13];
    const float* b1    = (const float*)d_in[14];
    const float* w2    = (const float*)d_in[15];
    const float* b2    = (const float*)d_in[16];
    float* out = (float*)d_out;

    float *T1, *BO;
    __nv_bfloat16 *Ch, *Cl, *Yh, *Yl, *Fh, *Fl, *WOh, *WOl, *W1Th, *W1Tl, *W2Th, *W2Tl;
    cudaGetSymbolAddress((void**)&T1,  g_T1);
    cudaGetSymbolAddress((void**)&BO,  g_BO);
    cudaGetSymbolAddress((void**)&Ch,  g_Ctxh);
    cudaGetSymbolAddress((void**)&Cl,  g_Ctxl);
    cudaGetSymbolAddress((void**)&Yh,  g_Yh);
    cudaGetSymbolAddress((void**)&Yl,  g_Yl);
    cudaGetSymbolAddress((void**)&Fh,  g_Fh);
    cudaGetSymbolAddress((void**)&Fl,  g_Fl);
    cudaGetSymbolAddress((void**)&WOh, g_WOh);
    cudaGetSymbolAddress((void**)&WOl, g_WOl);
    cudaGetSymbolAddress((void**)&W1Th, g_W1Th);
    cudaGetSymbolAddress((void**)&W1Tl, g_W1Tl);
    cudaGetSymbolAddress((void**)&W2Th, g_W2Th);
    cudaGetSymbolAddress((void**)&W2Tl, g_W2Tl);

    cudaFuncSetAttribute(k_gemm<0>, cudaFuncAttributeMaxDynamicSharedMemorySize, GSMEM_BYTES);
    cudaFuncSetAttribute(k_gemm<1>, cudaFuncAttributeMaxDynamicSharedMemorySize, GSMEM_BYTES);
    cudaFuncSetAttribute(k_gemm<2>, cudaFuncAttributeMaxDynamicSharedMemorySize, GSMEM_BYTES);

    k_detect_mask<<<1, 256>>>((const unsigned int*)masks);
    k_addpe<<<(B_*S_*H_)/256, 256>>>(tok);
    k_precompute<<<1, 256>>>(dq, wq, wk, bqkv, wo, bo);
    k_prep<<<2816, 256>>>(wv, wo, w1, w2);
    k_span<<<NSPAN/8, 256>>>(sids, masks);

    // GEMM1': T1 = Ctx(32768x256) @ WO^T (N=256) + BO
    k_gemm<0><<<dim3(2, NSPAN/128), 256, GSMEM_BYTES>>>(Ch, Cl, WOh, WOl, BO, T1,
                                                        nullptr, nullptr, nullptr, nullptr, H_, H_);
    // Y = LN(T1) -> bf16 hi/lo
    k_ln_bf16<<<NSPAN/8, 256>>>(T1, Yh, Yl, lng, lnb);
    // GEMM2: F = relu(Y @ W1T^T (N=1024) + b1) -> bf16 hi/lo
    k_gemm<1><<<dim3(8, NSPAN/128), 256, GSMEM_BYTES>>>(Yh, Yl, W1Th, W1Tl, b1, nullptr,
                                                        Fh, Fl, nullptr, nullptr, H_, FF_);
    // GEMM3: T1 = F @ W2T^T (N=256) + b2 + Y
    k_gemm<2><<<dim3(2, NSPAN/128), 256, GSMEM_BYTES>>>(Fh, Fl, W2Th, W2Tl, b2, T1,
                                                        nullptr, nullptr, Yh, Yl, FF_, H_);
    // out = LN(T1) * mask
    k_ln_final<<<NSPAN/8, 256>>>(T1, out, lng, lnb, masks);
}